// round 9
// baseline (speedup 1.0000x reference)
#include <cuda_runtime.h>
#include <cuda_bf16.h>
#include <math.h>
#include <stdint.h>

#define B 2
#define L 2048
#define D 2048
#define H 16
#define HKV 4
#define HD 128
#define GROUPS (H / HKV)
#define M_TOK (B * L)          // 4096 tokens
#define KVDIM (2 * HKV * HD)   // 1024
#define KDIM  (HKV * HD)       // 512
#define QKVD (D + KVDIM)       // 3072 fused projection width
#define SCALE 0.08838834764831845f

// ---------------- scratch (static device arrays) ---------------------------
__device__ float g_QKV[(size_t)M_TOK * QKVD];  // fused Q|KV proj out (fp32)
__device__ float g_bqkv[QKVD];                 // concat bias
__device__ __nv_bfloat16 g_xh[(size_t)M_TOK * D];
__device__ __nv_bfloat16 g_xl[(size_t)M_TOK * D];
__device__ __nv_bfloat16 g_wch[(size_t)QKVD * D];   // concat Wq|Wkv hi
__device__ __nv_bfloat16 g_wcl[(size_t)QKVD * D];   // concat Wq|Wkv lo
__device__ __nv_bfloat16 g_woh[(size_t)D * D];
__device__ __nv_bfloat16 g_wol[(size_t)D * D];
__device__ __nv_bfloat16 g_qh[(size_t)M_TOK * D];
__device__ __nv_bfloat16 g_ql[(size_t)M_TOK * D];
__device__ __nv_bfloat16 g_kh[(size_t)M_TOK * KDIM];
__device__ __nv_bfloat16 g_kl[(size_t)M_TOK * KDIM];
__device__ __nv_bfloat16 g_vh[(size_t)M_TOK * KDIM];
__device__ __nv_bfloat16 g_vl[(size_t)M_TOK * KDIM];
__device__ __nv_bfloat16 g_ah[(size_t)M_TOK * D];
__device__ __nv_bfloat16 g_al[(size_t)M_TOK * D];

// ======================= helpers ==========================================
__device__ __forceinline__ uint32_t smem_u32(const void* p) {
    uint32_t a;
    asm("{ .reg .u64 t; cvta.to.shared.u64 t, %1; cvt.u32.u64 %0, t; }"
        : "=r"(a) : "l"(p));
    return a;
}
// 64B-pitch tile swizzle: 16B chunk c16 ^= (row>>1)&3  (conflict-free for
// ldmatrix 8-address phases and for warp cp.async stores; verified mod-8).
#define SWZ64(off) ((off) ^ ((((off) >> 7) & 3u) << 4))

__device__ __forceinline__ void ldsm4(uint32_t addr, uint32_t* r) {
    asm volatile("ldmatrix.sync.aligned.m8n8.x4.shared.b16 {%0,%1,%2,%3}, [%4];"
                 : "=r"(r[0]), "=r"(r[1]), "=r"(r[2]), "=r"(r[3]) : "r"(addr));
}
__device__ __forceinline__ void ldsm4t(uint32_t addr, uint32_t* r) {
    asm volatile("ldmatrix.sync.aligned.m8n8.x4.trans.shared.b16 {%0,%1,%2,%3}, [%4];"
                 : "=r"(r[0]), "=r"(r[1]), "=r"(r[2]), "=r"(r[3]) : "r"(addr));
}
__device__ __forceinline__ void mma_bf16(float* c, const uint32_t* a,
                                         const uint32_t* b) {
    asm volatile(
        "mma.sync.aligned.m16n8k16.row.col.f32.bf16.bf16.f32 "
        "{%0,%1,%2,%3}, {%4,%5,%6,%7}, {%8,%9}, {%0,%1,%2,%3};"
        : "+f"(c[0]), "+f"(c[1]), "+f"(c[2]), "+f"(c[3])
        : "r"(a[0]), "r"(a[1]), "r"(a[2]), "r"(a[3]), "r"(b[0]), "r"(b[1]));
}
__device__ __forceinline__ void cp_async16(uint32_t dst, const void* src) {
    asm volatile("cp.async.cg.shared.global [%0], [%1], 16;"
                 :: "r"(dst), "l"(src));
}
#define CP_COMMIT() asm volatile("cp.async.commit_group;" ::: "memory")
#define CP_WAIT(N)  asm volatile("cp.async.wait_group %0;" :: "n"(N) : "memory")

__device__ __forceinline__ uint32_t pack_bf16x2(float lo, float hi) {
    uint32_t r;
    asm("cvt.rn.bf16x2.f32 %0, %1, %2;" : "=r"(r) : "f"(hi), "f"(lo));
    return r;
}
__device__ __forceinline__ float bf16_round(float x) {
    return __bfloat162float(__float2bfloat16(x));
}

// ======================= fused hi/lo split (x + weights + bias) ===========
#define N4_X   ((M_TOK * D) / 4)
#define N4_WQ  ((D * D) / 4)
#define N4_WKV ((KVDIM * D) / 4)
#define N4_WO  ((D * D) / 4)
#define N4_BIA (QKVD / 4)
#define N4_TOT (N4_X + N4_WQ + N4_WKV + N4_WO + N4_BIA)

__device__ __forceinline__ void split4(const float* __restrict__ src,
                                       __nv_bfloat16* __restrict__ hi,
                                       __nv_bfloat16* __restrict__ lo, int i) {
    float4 v = ((const float4*)src)[i];
    float h0 = bf16_round(v.x), h1 = bf16_round(v.y);
    float h2 = bf16_round(v.z), h3 = bf16_round(v.w);
    uint32_t* hp = (uint32_t*)hi;
    uint32_t* lp = (uint32_t*)lo;
    hp[2 * i]     = pack_bf16x2(v.x, v.y);
    hp[2 * i + 1] = pack_bf16x2(v.z, v.w);
    lp[2 * i]     = pack_bf16x2(v.x - h0, v.y - h1);
    lp[2 * i + 1] = pack_bf16x2(v.z - h2, v.w - h3);
}

__global__ __launch_bounds__(256) void cvt_all(
    const float* __restrict__ x,  const float* __restrict__ Wq,
    const float* __restrict__ Wkv, const float* __restrict__ Wo,
    const float* __restrict__ bq,  const float* __restrict__ bkv,
    __nv_bfloat16* __restrict__ xh,  __nv_bfloat16* __restrict__ xl,
    __nv_bfloat16* __restrict__ wch, __nv_bfloat16* __restrict__ wcl,
    __nv_bfloat16* __restrict__ woh, __nv_bfloat16* __restrict__ wol,
    float* __restrict__ bqkv)
{
    int i = blockIdx.x * blockDim.x + threadIdx.x;
    if (i < N4_X) { split4(x, xh, xl, i); return; }
    i -= N4_X;
    if (i < N4_WQ) { split4(Wq, wch, wcl, i); return; }     // rows 0..2047
    i -= N4_WQ;
    if (i < N4_WKV) { split4(Wkv, wch + (size_t)D * D, wcl + (size_t)D * D, i); return; }
    i -= N4_WKV;
    if (i < N4_WO) { split4(Wo, woh, wol, i); return; }
    i -= N4_WO;
    if (i < N4_BIA) {
        float4 v = (i < D / 4) ? ((const float4*)bq)[i]
                               : ((const float4*)bkv)[i - D / 4];
        ((float4*)bqkv)[i] = v;
    }
}

// ======================= mma.sync bf16x3 GEMM =============================
// 128x128 CTA tile, GBK=32, 64B-pitch smem tiles, 3 stages (96KB) -> 2 CTA/SM
#define GK 2048
#define GBK 32
#define NCHUNK (GK / GBK)           // 64
#define TILE_B 8192                 // 128 rows * 64B
#define STAGE_B (4 * TILE_B)        // 32768

__global__ __launch_bounds__(256, 2) void gemm_bf16x3(
    const __nv_bfloat16* __restrict__ Ah, const __nv_bfloat16* __restrict__ Al,
    const __nv_bfloat16* __restrict__ Wh, const __nv_bfloat16* __restrict__ Wl,
    const float* __restrict__ bias, float* __restrict__ C, int Ndim)
{
    extern __shared__ char smem_raw[];
    const uint32_t tiles_u32 = smem_u32(smem_raw);

    const int tid  = threadIdx.x;
    const int wid  = tid >> 5;
    const int lane = tid & 31;
    const int bm = blockIdx.y * 128;
    const int bn = blockIdx.x * 128;
    const int wm = (wid & 3) * 32;
    const int wn = (wid >> 2) * 64;

    const __nv_bfloat16* srcs[4] = {Ah, Al, Wh, Wl};

    // 2048 16B-chunks per stage / 256 threads = 8 per thread
    auto load_chunk = [&](int k0, int s) {
        const uint32_t sb = tiles_u32 + s * STAGE_B;
#pragma unroll
        for (int j = 0; j < 8; j++) {
            int e = tid + j * 256;
            int t   = e >> 9;            // tile 0..3
            int r   = (e >> 2) & 127;    // row
            int c16 = e & 3;             // 16B chunk in row
            int row = (t < 2 ? bm : bn) + r;
            const void* src = &srcs[t][(size_t)row * GK + k0 + c16 * 8];
            uint32_t off = SWZ64((uint32_t)(r * 64 + c16 * 16));
            cp_async16(sb + t * TILE_B + off, src);
        }
    };

    float c[2][8][4];
#pragma unroll
    for (int mt = 0; mt < 2; mt++)
#pragma unroll
        for (int nt = 0; nt < 8; nt++)
#pragma unroll
            for (int q = 0; q < 4; q++) c[mt][nt][q] = 0.f;

    const int mi = lane >> 3, rr = lane & 7;

    load_chunk(0, 0);        CP_COMMIT();
    load_chunk(GBK, 1);      CP_COMMIT();

    for (int i = 0; i < NCHUNK; i++) {
        CP_WAIT(1);
        __syncthreads();
        if (i + 2 < NCHUNK) load_chunk((i + 2) * GBK, (i + 2) % 3);
        CP_COMMIT();

        const uint32_t st   = tiles_u32 + (i % 3) * STAGE_B;
        const uint32_t Ah_b = st;
        const uint32_t Al_b = st + TILE_B;
        const uint32_t Wh_b = st + 2 * TILE_B;
        const uint32_t Wl_b = st + 3 * TILE_B;

#pragma unroll
        for (int k16 = 0; k16 < 2; k16++) {
            const int kb = k16 * 16;
            uint32_t ah[2][4], al[2][4], bh[4][4], bl[4][4];
#pragma unroll
            for (int mt = 0; mt < 2; mt++) {
                const int m = wm + mt * 16 + (mi & 1) * 8 + rr;
                const int k = kb + (mi >> 1) * 8;
                const uint32_t off = SWZ64((uint32_t)(m * 64 + k * 2));
                ldsm4(Ah_b + off, ah[mt]);
                ldsm4(Al_b + off, al[mt]);
            }
#pragma unroll
            for (int np = 0; np < 4; np++) {
                const int n = wn + np * 16 + (mi >> 1) * 8 + rr;
                const int k = kb + (mi & 1) * 8;
                const uint32_t off = SWZ64((uint32_t)(n * 64 + k * 2));
                ldsm4(Wh_b + off, bh[np]);
                ldsm4(Wl_b + off, bl[np]);
            }
#pragma unroll
            for (int mt = 0; mt < 2; mt++)
#pragma unroll
                for (int nt = 0; nt < 8; nt++) {
                    const uint32_t* bhp = &bh[nt >> 1][(nt & 1) * 2];
                    const uint32_t* blp = &bl[nt >> 1][(nt & 1) * 2];
                    mma_bf16(c[mt][nt], ah[mt], bhp);
                    mma_bf16(c[mt][nt], ah[mt], blp);
                    mma_bf16(c[mt][nt], al[mt], bhp);
                }
        }
    }

#pragma unroll
    for (int mt = 0; mt < 2; mt++) {
        const int row0 = bm + wm + mt * 16 + (lane >> 2);
#pragma unroll
        for (int nt = 0; nt < 8; nt++) {
            const int col = bn + wn + nt * 8 + (lane & 3) * 2;
            const float b0 = bias[col], b1 = bias[col + 1];
            float2 v0 = make_float2(c[mt][nt][0] + b0, c[mt][nt][1] + b1);
            float2 v1 = make_float2(c[mt][nt][2] + b0, c[mt][nt][3] + b1);
            *(float2*)&C[(size_t)row0 * Ndim + col]       = v0;
            *(float2*)&C[(size_t)(row0 + 8) * Ndim + col] = v1;
        }
    }
}

// ======================= RoPE + split to bf16 hi/lo =======================
__global__ __launch_bounds__(256) void rope_split_cvt(
    const float* __restrict__ cosb, const float* __restrict__ sinb,
    const float* __restrict__ QKV,
    __nv_bfloat16* __restrict__ qh, __nv_bfloat16* __restrict__ ql,
    __nv_bfloat16* __restrict__ kh, __nv_bfloat16* __restrict__ kl,
    __nv_bfloat16* __restrict__ vh, __nv_bfloat16* __restrict__ vl)
{
    const int tok = blockIdx.x;
    const int tid = threadIdx.x;
    const float* c = cosb + (size_t)tok * HD;
    const float* s = sinb + (size_t)tok * HD;
    const float* Qr  = QKV + (size_t)tok * QKVD;
    const float* KVr = Qr + D;

    for (int p = tid; p < H * 64; p += 256) {
        const int h = p >> 6, d = p & 63;
        const size_t ob = (size_t)tok * D + h * HD;
        const float a = Qr[h * HD + d], b2 = Qr[h * HD + d + 64];
        const float e0 = (a  * c[d]      - b2 * s[d])      * SCALE;
        const float e1 = (b2 * c[d + 64] + a  * s[d + 64]) * SCALE;
        const float h0 = bf16_round(e0), h1 = bf16_round(e1);
        qh[ob + d]      = __float2bfloat16(h0);
        qh[ob + d + 64] = __float2bfloat16(h1);
        ql[ob + d]      = __float2bfloat16(e0 - h0);
        ql[ob + d + 64] = __float2bfloat16(e1 - h1);
    }
    for (int p = tid; p < HKV * 64; p += 256) {
        const int h = p >> 6, d = p & 63;
        const size_t ob = (size_t)tok * KDIM + h * HD;
        const float a = KVr[h * HD + d], b2 = KVr[h * HD + d + 64];
        const float e0 = a  * c[d]      - b2 * s[d];
        const float e1 = b2 * c[d + 64] + a  * s[d + 64];
        const float h0 = bf16_round(e0), h1 = bf16_round(e1);
        kh[ob + d]      = __float2bfloat16(h0);
        kh[ob + d + 64] = __float2bfloat16(h1);
        kl[ob + d]      = __float2bfloat16(e0 - h0);
        kl[ob + d + 64] = __float2bfloat16(e1 - h1);
    }
    for (int e = tid; e < KDIM; e += 256) {
        const float v = KVr[KDIM + e];
        const float h0 = bf16_round(v);
        vh[(size_t)tok * KDIM + e] = __float2bfloat16(h0);
        vl[(size_t)tok * KDIM + e] = __float2bfloat16(v - h0);
    }
}

// ======================= flash attention (tensor cores, bf16x3) ===========
#define FBM 128
#define FBN 64
#define KP  136
#define KT_BYTES (FBN * KP * 2)       // 17408
#define FSTG (4 * KT_BYTES)

__global__ __launch_bounds__(256, 1) void flash_mma(
    const __nv_bfloat16* __restrict__ Qh, const __nv_bfloat16* __restrict__ Ql,
    const __nv_bfloat16* __restrict__ Kh, const __nv_bfloat16* __restrict__ Kl,
    const __nv_bfloat16* __restrict__ Vh, const __nv_bfloat16* __restrict__ Vl,
    __nv_bfloat16* __restrict__ Ah, __nv_bfloat16* __restrict__ Al)
{
    extern __shared__ char smem_raw[];
    const uint32_t smem = smem_u32(smem_raw);

    const int tid  = threadIdx.x;
    const int w    = tid >> 5;
    const int lane = tid & 31;
    const int m0   = blockIdx.x * FBM;
    const int bh   = blockIdx.y;
    const int b    = bh / H;
    const int h    = bh % H;
    const int kvh  = h / GROUPS;

    const int rowg0 = m0 + w * 16 + (lane >> 2);
    const int rowg1 = rowg0 + 8;

    uint32_t qh[8][4], ql[8][4];
    {
        const size_t base0 = ((size_t)(b * L + rowg0) * H + h) * HD;
        const size_t base1 = base0 + (size_t)8 * H * HD;
#pragma unroll
        for (int j = 0; j < 8; j++) {
            const int c0 = j * 16 + (lane & 3) * 2;
            qh[j][0] = *(const uint32_t*)&Qh[base0 + c0];
            qh[j][1] = *(const uint32_t*)&Qh[base1 + c0];
            qh[j][2] = *(const uint32_t*)&Qh[base0 + c0 + 8];
            qh[j][3] = *(const uint32_t*)&Qh[base1 + c0 + 8];
            ql[j][0] = *(const uint32_t*)&Ql[base0 + c0];
            ql[j][1] = *(const uint32_t*)&Ql[base1 + c0];
            ql[j][2] = *(const uint32_t*)&Ql[base0 + c0 + 8];
            ql[j][3] = *(const uint32_t*)&Ql[base1 + c0 + 8];
        }
    }

    const __nv_bfloat16* kvsrc[4] = {Kh, Kl, Vh, Vl};
    auto load_kv = [&](int t, int s) {
        const int n0 = t * FBN;
        const uint32_t sb = smem + s * FSTG;
#pragma unroll
        for (int jj = 0; jj < 16; jj++) {
            int e = tid + jj * 256;
            int buf = e >> 10;
            int r   = (e >> 4) & 63;
            int ch  = e & 15;
            const void* src =
                &kvsrc[buf][((size_t)(b * L + n0 + r) * HKV + kvh) * HD + ch * 8];
            uint32_t dst = sb + buf * KT_BYTES + (uint32_t)(r * KP + ch * 8) * 2;
            cp_async16(dst, src);
        }
    };

    float o[16][4];
#pragma unroll
    for (int nt = 0; nt < 16; nt++)
#pragma unroll
        for (int q = 0; q < 4; q++) o[nt][q] = 0.f;
    float mrow0 = -1e30f, mrow1 = -1e30f, lrow0 = 0.f, lrow1 = 0.f;

    const int ntiles = m0 / FBN + 2;
    load_kv(0, 0);
    CP_COMMIT();

    const int rlane = lane & 7;
    const int khalf = (lane >> 3) & 1;
    const int npair = lane >> 4;

    for (int t = 0; t < ntiles; t++) {
        CP_WAIT(0);
        __syncthreads();
        if (t + 1 < ntiles) load_kv(t + 1, (t + 1) & 1);
        CP_COMMIT();

        const int n0 = t * FBN;
        if (n0 > m0 + w * 16 + 15) continue;

        const uint32_t st  = smem + (t & 1) * FSTG;
        const uint32_t Khs = st;
        const uint32_t Kls = st + KT_BYTES;
        const uint32_t Vhs = st + 2 * KT_BYTES;
        const uint32_t Vls = st + 3 * KT_BYTES;

        float s8[8][4];
#pragma unroll
        for (int nt = 0; nt < 8; nt++)
#pragma unroll
            for (int q = 0; q < 4; q++) s8[nt][q] = 0.f;

#pragma unroll
        for (int j = 0; j < 8; j++) {
#pragma unroll
            for (int nt = 0; nt < 8; nt += 2) {
                uint32_t kb4[4], kl4[4];
                const uint32_t a = (uint32_t)(((nt + npair) * 8 + rlane) * KP
                                              + j * 16 + khalf * 8) * 2;
                ldsm4(Khs + a, kb4);
                ldsm4(Kls + a, kl4);
                mma_bf16(s8[nt],     qh[j], kb4);
                mma_bf16(s8[nt],     qh[j], kl4);
                mma_bf16(s8[nt],     ql[j], kb4);
                mma_bf16(s8[nt + 1], qh[j], kb4 + 2);
                mma_bf16(s8[nt + 1], qh[j], kl4 + 2);
                mma_bf16(s8[nt + 1], ql[j], kb4 + 2);
            }
        }

        if (t >= ntiles - 2) {
            const int colc = n0 + (lane & 3) * 2;
#pragma unroll
            for (int nt = 0; nt < 8; nt++) {
                const int cg = colc + nt * 8;
                if (cg     > rowg0) s8[nt][0] = -1e30f;
                if (cg + 1 > rowg0) s8[nt][1] = -1e30f;
                if (cg     > rowg1) s8[nt][2] = -1e30f;
                if (cg + 1 > rowg1) s8[nt][3] = -1e30f;
            }
        }

        float mx0 = -1e30f, mx1 = -1e30f;
#pragma unroll
        for (int nt = 0; nt < 8; nt++) {
            mx0 = fmaxf(mx0, fmaxf(s8[nt][0], s8[nt][1]));
            mx1 = fmaxf(mx1, fmaxf(s8[nt][2], s8[nt][3]));
        }
        mx0 = fmaxf(mx0, __shfl_xor_sync(0xffffffffu, mx0, 1));
        mx0 = fmaxf(mx0, __shfl_xor_sync(0xffffffffu, mx0, 2));
        mx1 = fmaxf(mx1, __shfl_xor_sync(0xffffffffu, mx1, 1));
        mx1 = fmaxf(mx1, __shfl_xor_sync(0xffffffffu, mx1, 2));

        const float mn0 = fmaxf(mrow0, mx0);
        const float mn1 = fmaxf(mrow1, mx1);
        const float alpha0 = __expf(mrow0 - mn0);
        const float alpha1 = __expf(mrow1 - mn1);

        float sum0 = 0.f, sum1 = 0.f;
#pragma unroll
        for (int nt = 0; nt < 8; nt++) {
            s8[nt][0] = __expf(s8[nt][0] - mn0);
            s8[nt][1] = __expf(s8[nt][1] - mn0);
            s8[nt][2] = __expf(s8[nt][2] - mn1);
            s8[nt][3] = __expf(s8[nt][3] - mn1);
            sum0 += s8[nt][0] + s8[nt][1];
            sum1 += s8[nt][2] + s8[nt][3];
        }
        sum0 += __shfl_xor_sync(0xffffffffu, sum0, 1);
        sum0 += __shfl_xor_sync(0xffffffffu, sum0, 2);
        sum1 += __shfl_xor_sync(0xffffffffu, sum1, 1);
        sum1 += __shfl_xor_sync(0xffffffffu, sum1, 2);

        lrow0 = lrow0 * alpha0 + sum0;
        lrow1 = lrow1 * alpha1 + sum1;
        mrow0 = mn0; mrow1 = mn1;

#pragma unroll
        for (int nt = 0; nt < 16; nt++) {
            o[nt][0] *= alpha0; o[nt][1] *= alpha0;
            o[nt][2] *= alpha1; o[nt][3] *= alpha1;
        }

#pragma unroll
        for (int kt = 0; kt < 4; kt++) {
            uint32_t ph4[4], pl4[4];
            {
                const float* p0 = s8[2 * kt];
                const float* p1 = s8[2 * kt + 1];
                float h;
                h = bf16_round(p0[0]); float l00 = p0[0] - h;
                h = bf16_round(p0[1]); float l01 = p0[1] - h;
                h = bf16_round(p0[2]); float l02 = p0[2] - h;
                h = bf16_round(p0[3]); float l03 = p0[3] - h;
                ph4[0] = pack_bf16x2(p0[0], p0[1]);
                ph4[1] = pack_bf16x2(p0[2], p0[3]);
                pl4[0] = pack_bf16x2(l00, l01);
                pl4[1] = pack_bf16x2(l02, l03);
                h = bf16_round(p1[0]); float l10 = p1[0] - h;
                h = bf16_round(p1[1]); float l11 = p1[1] - h;
                h = bf16_round(p1[2]); float l12 = p1[2] - h;
                h = bf16_round(p1[3]); float l13 = p1[3] - h;
                ph4[2] = pack_bf16x2(p1[0], p1[1]);
                ph4[3] = pack_bf16x2(p1[2], p1[3]);
                pl4[2] = pack_bf16x2(l10, l11);
                pl4[3] = pack_bf16x2(l12, l13);
            }
#pragma unroll
            for (int nt = 0; nt < 16; nt += 2) {
                uint32_t vh4[4], vl4[4];
                const uint32_t a = (uint32_t)((kt * 16 + khalf * 8 + rlane) * KP
                                              + (nt + npair) * 8) * 2;
                ldsm4t(Vhs + a, vh4);
                ldsm4t(Vls + a, vl4);
                mma_bf16(o[nt],     ph4, vh4);
                mma_bf16(o[nt],     ph4, vl4);
                mma_bf16(o[nt],     pl4, vh4);
                mma_bf16(o[nt + 1], ph4, vh4 + 2);
                mma_bf16(o[nt + 1], ph4, vl4 + 2);
                mma_bf16(o[nt + 1], pl4, vh4 + 2);
            }
        }
    }

    const float inv0 = 1.f / lrow0;
    const float inv1 = 1.f / lrow1;
    const size_t base0 = ((size_t)(b * L + rowg0) * H + h) * HD;
    const size_t base1 = base0 + (size_t)8 * H * HD;
#pragma unroll
    for (int nt = 0; nt < 16; nt++) {
        const int col = nt * 8 + (lane & 3) * 2;
        const float f0 = o[nt][0] * inv0, f1 = o[nt][1] * inv0;
        const float f2 = o[nt][2] * inv1, f3 = o[nt][3] * inv1;
        const float h0 = bf16_round(f0), h1 = bf16_round(f1);
        const float h2 = bf16_round(f2), h3 = bf16_round(f3);
        *(uint32_t*)&Ah[base0 + col] = pack_bf16x2(f0, f1);
        *(uint32_t*)&Ah[base1 + col] = pack_bf16x2(f2, f3);
        *(uint32_t*)&Al[base0 + col] = pack_bf16x2(f0 - h0, f1 - h1);
        *(uint32_t*)&Al[base1 + col] = pack_bf16x2(f2 - h2, f3 - h3);
    }
}

// ===========================================================================
extern "C" void kernel_launch(void* const* d_in, const int* in_sizes, int n_in,
                              void* d_out, int out_size)
{
    (void)in_sizes; (void)n_in; (void)out_size;
    const float* x    = (const float*)d_in[0];
    const float* cosb = (const float*)d_in[1];
    const float* sinb = (const float*)d_in[2];
    const float* Wq   = (const float*)d_in[3];
    const float* bq   = (const float*)d_in[4];
    const float* Wkv  = (const float*)d_in[5];
    const float* bkv  = (const float*)d_in[6];
    const float* Wo   = (const float*)d_in[7];
    const float* bo   = (const float*)d_in[8];
    float* out = (float*)d_out;

    float *QKVb, *bqkv;
    __nv_bfloat16 *xh, *xl, *wch, *wcl, *woh, *wol;
    __nv_bfloat16 *qh, *ql, *kh, *kl, *vh, *vl, *ah, *al;
    cudaGetSymbolAddress((void**)&QKVb, g_QKV);
    cudaGetSymbolAddress((void**)&bqkv, g_bqkv);
    cudaGetSymbolAddress((void**)&xh,  g_xh);
    cudaGetSymbolAddress((void**)&xl,  g_xl);
    cudaGetSymbolAddress((void**)&wch, g_wch);
    cudaGetSymbolAddress((void**)&wcl, g_wcl);
    cudaGetSymbolAddress((void**)&woh, g_woh);
    cudaGetSymbolAddress((void**)&wol, g_wol);
    cudaGetSymbolAddress((void**)&qh,  g_qh);
    cudaGetSymbolAddress((void**)&ql,  g_ql);
    cudaGetSymbolAddress((void**)&kh,  g_kh);
    cudaGetSymbolAddress((void**)&kl,  g_kl);
    cudaGetSymbolAddress((void**)&vh,  g_vh);
    cudaGetSymbolAddress((void**)&vl,  g_vl);
    cudaGetSymbolAddress((void**)&ah,  g_ah);
    cudaGetSymbolAddress((void**)&al,  g_al);

    const int gemm_smem = 3 * STAGE_B;          // 96 KB
    cudaFuncSetAttribute(gemm_bf16x3, cudaFuncAttributeMaxDynamicSharedMemorySize,
                         gemm_smem);
    const int fa_smem = 2 * FSTG;
    cudaFuncSetAttribute(flash_mma, cudaFuncAttributeMaxDynamicSharedMemorySize,
                         fa_smem);

    // one fused conversion: x + concat(Wq,Wkv) + Wo + concat bias
    cvt_all<<<(N4_TOT + 255) / 256, 256>>>(x, Wq, Wkv, Wo, bq, bkv,
                                           xh, xl, wch, wcl, woh, wol, bqkv);

    // fused Q|KV projection (N = 3072)
    gemm_bf16x3<<<dim3(QKVD / 128, M_TOK / 128), 256, gemm_smem>>>(
        xh, xl, wch, wcl, bqkv, QKVb, QKVD);

    // RoPE + split to bf16 hi/lo (scale folded into Q)
    rope_split_cvt<<<M_TOK, 256>>>(cosb, sinb, QKVb, qh, ql, kh, kl, vh, vl);

    // tensor-core flash attention -> Ah/Al splits
    flash_mma<<<dim3(L / FBM, B * H), 256, fa_smem>>>(
        qh, ql, kh, kl, vh, vl, ah, al);

    // O projection
    gemm_bf16x3<<<dim3(D / 128, M_TOK / 128), 256, gemm_smem>>>(
        ah, al, woh, wol, bo, out, D);
}

// round 11
// speedup vs baseline: 1.0605x; 1.0605x over previous
#include <cuda_runtime.h>
#include <cuda_bf16.h>
#include <cuda_fp16.h>
#include <math.h>
#include <stdint.h>

#define B 2
#define L 2048
#define D 2048
#define H 16
#define HKV 4
#define HD 128
#define GROUPS (H / HKV)
#define M_TOK (B * L)          // 4096 tokens
#define KVDIM (2 * HKV * HD)   // 1024
#define KDIM  (HKV * HD)       // 512
#define QKVD (D + KVDIM)       // 3072 fused projection width
#define SCALE 0.08838834764831845f

// ---------------- scratch (static device arrays) ---------------------------
__device__ float g_QKV[(size_t)M_TOK * QKVD];  // fused Q|KV proj out (fp32)
__device__ float g_bqkv[QKVD];                 // concat bias
__device__ __nv_bfloat16 g_xh[(size_t)M_TOK * D];
__device__ __nv_bfloat16 g_xl[(size_t)M_TOK * D];
__device__ __nv_bfloat16 g_wch[(size_t)QKVD * D];   // concat Wq|Wkv hi
__device__ __nv_bfloat16 g_wcl[(size_t)QKVD * D];   // concat Wq|Wkv lo
__device__ __nv_bfloat16 g_woh[(size_t)D * D];
__device__ __nv_bfloat16 g_wol[(size_t)D * D];
__device__ __nv_bfloat16 g_qh[(size_t)M_TOK * D];
__device__ __nv_bfloat16 g_ql[(size_t)M_TOK * D];
__device__ __nv_bfloat16 g_kh[(size_t)M_TOK * KDIM];
__device__ __nv_bfloat16 g_kl[(size_t)M_TOK * KDIM];
__device__ __half g_vh[(size_t)M_TOK * KDIM];       // V hi (fp16)
__device__ __half g_vl[(size_t)M_TOK * KDIM];       // V lo (fp16)
__device__ __nv_bfloat16 g_ah[(size_t)M_TOK * D];
__device__ __nv_bfloat16 g_al[(size_t)M_TOK * D];

// ======================= helpers ==========================================
__device__ __forceinline__ uint32_t smem_u32(const void* p) {
    uint32_t a;
    asm("{ .reg .u64 t; cvta.to.shared.u64 t, %1; cvt.u32.u64 %0, t; }"
        : "=r"(a) : "l"(p));
    return a;
}
#define SWZ128(off) ((off) ^ (((off) >> 3) & 0x70))

__device__ __forceinline__ void ldsm4(uint32_t addr, uint32_t* r) {
    asm volatile("ldmatrix.sync.aligned.m8n8.x4.shared.b16 {%0,%1,%2,%3}, [%4];"
                 : "=r"(r[0]), "=r"(r[1]), "=r"(r[2]), "=r"(r[3]) : "r"(addr));
}
__device__ __forceinline__ void ldsm4t(uint32_t addr, uint32_t* r) {
    asm volatile("ldmatrix.sync.aligned.m8n8.x4.trans.shared.b16 {%0,%1,%2,%3}, [%4];"
                 : "=r"(r[0]), "=r"(r[1]), "=r"(r[2]), "=r"(r[3]) : "r"(addr));
}
__device__ __forceinline__ void mma_bf16(float* c, const uint32_t* a,
                                         const uint32_t* b) {
    asm volatile(
        "mma.sync.aligned.m16n8k16.row.col.f32.bf16.bf16.f32 "
        "{%0,%1,%2,%3}, {%4,%5,%6,%7}, {%8,%9}, {%0,%1,%2,%3};"
        : "+f"(c[0]), "+f"(c[1]), "+f"(c[2]), "+f"(c[3])
        : "r"(a[0]), "r"(a[1]), "r"(a[2]), "r"(a[3]), "r"(b[0]), "r"(b[1]));
}
__device__ __forceinline__ void mma_f16(float* c, const uint32_t* a,
                                        const uint32_t* b) {
    asm volatile(
        "mma.sync.aligned.m16n8k16.row.col.f32.f16.f16.f32 "
        "{%0,%1,%2,%3}, {%4,%5,%6,%7}, {%8,%9}, {%0,%1,%2,%3};"
        : "+f"(c[0]), "+f"(c[1]), "+f"(c[2]), "+f"(c[3])
        : "r"(a[0]), "r"(a[1]), "r"(a[2]), "r"(a[3]), "r"(b[0]), "r"(b[1]));
}
__device__ __forceinline__ void cp_async16(uint32_t dst, const void* src) {
    asm volatile("cp.async.cg.shared.global [%0], [%1], 16;"
                 :: "r"(dst), "l"(src));
}
#define CP_COMMIT() asm volatile("cp.async.commit_group;" ::: "memory")
#define CP_WAIT(N)  asm volatile("cp.async.wait_group %0;" :: "n"(N) : "memory")

__device__ __forceinline__ uint32_t pack_bf16x2(float lo, float hi) {
    uint32_t r;
    asm("cvt.rn.bf16x2.f32 %0, %1, %2;" : "=r"(r) : "f"(hi), "f"(lo));
    return r;
}
__device__ __forceinline__ uint32_t pack_f16x2(float lo, float hi) {
    uint32_t r;
    asm("cvt.rn.f16x2.f32 %0, %1, %2;" : "=r"(r) : "f"(hi), "f"(lo));
    return r;
}
__device__ __forceinline__ float bf16_round(float x) {
    return __bfloat162float(__float2bfloat16(x));
}

// ======================= fused hi/lo split (x + weights + bias) ===========
#define N4_X   ((M_TOK * D) / 4)
#define N4_WQ  ((D * D) / 4)
#define N4_WKV ((KVDIM * D) / 4)
#define N4_WO  ((D * D) / 4)
#define N4_BIA (QKVD / 4)
#define N4_TOT (N4_X + N4_WQ + N4_WKV + N4_WO + N4_BIA)

__device__ __forceinline__ void split4(const float* __restrict__ src,
                                       __nv_bfloat16* __restrict__ hi,
                                       __nv_bfloat16* __restrict__ lo, int i) {
    float4 v = ((const float4*)src)[i];
    float h0 = bf16_round(v.x), h1 = bf16_round(v.y);
    float h2 = bf16_round(v.z), h3 = bf16_round(v.w);
    uint32_t* hp = (uint32_t*)hi;
    uint32_t* lp = (uint32_t*)lo;
    hp[2 * i]     = pack_bf16x2(v.x, v.y);
    hp[2 * i + 1] = pack_bf16x2(v.z, v.w);
    lp[2 * i]     = pack_bf16x2(v.x - h0, v.y - h1);
    lp[2 * i + 1] = pack_bf16x2(v.z - h2, v.w - h3);
}

__global__ __launch_bounds__(256) void cvt_all(
    const float* __restrict__ x,  const float* __restrict__ Wq,
    const float* __restrict__ Wkv, const float* __restrict__ Wo,
    const float* __restrict__ bq,  const float* __restrict__ bkv,
    __nv_bfloat16* __restrict__ xh,  __nv_bfloat16* __restrict__ xl,
    __nv_bfloat16* __restrict__ wch, __nv_bfloat16* __restrict__ wcl,
    __nv_bfloat16* __restrict__ woh, __nv_bfloat16* __restrict__ wol,
    float* __restrict__ bqkv)
{
    int i = blockIdx.x * blockDim.x + threadIdx.x;
    if (i < N4_X) { split4(x, xh, xl, i); return; }
    i -= N4_X;
    if (i < N4_WQ) { split4(Wq, wch, wcl, i); return; }
    i -= N4_WQ;
    if (i < N4_WKV) { split4(Wkv, wch + (size_t)D * D, wcl + (size_t)D * D, i); return; }
    i -= N4_WKV;
    if (i < N4_WO) { split4(Wo, woh, wol, i); return; }
    i -= N4_WO;
    if (i < N4_BIA) {
        float4 v = (i < D / 4) ? ((const float4*)bq)[i]
                               : ((const float4*)bkv)[i - D / 4];
        ((float4*)bqkv)[i] = v;
    }
}

// ======================= mma.sync bf16x3 GEMM (R8 config) =================
#define GK 2048
#define GBK 64
#define NCHUNK (GK / GBK)           // 32
#define TILE_BYTES 16384            // 128 rows * 128B (64 bf16)
#define STAGE_BYTES (4 * TILE_BYTES)

__global__ __launch_bounds__(256, 1) void gemm_bf16x3(
    const __nv_bfloat16* __restrict__ Ah, const __nv_bfloat16* __restrict__ Al,
    const __nv_bfloat16* __restrict__ Wh, const __nv_bfloat16* __restrict__ Wl,
    const float* __restrict__ bias, float* __restrict__ C, int Ndim)
{
    extern __shared__ char smem_raw[];
    char* tiles = (char*)(((uintptr_t)smem_raw + 1023) & ~(uintptr_t)1023);
    const uint32_t tiles_u32 = smem_u32(tiles);

    const int tid  = threadIdx.x;
    const int wid  = tid >> 5;
    const int lane = tid & 31;
    const int bm = blockIdx.y * 128;
    const int bn = blockIdx.x * 128;
    const int wm = (wid & 3) * 32;
    const int wn = (wid >> 2) * 64;

    const __nv_bfloat16* srcs[4] = {Ah, Al, Wh, Wl};

    auto load_chunk = [&](int k0, int s) {
        const uint32_t sb = tiles_u32 + s * STAGE_BYTES;
#pragma unroll
        for (int j = 0; j < 16; j++) {
            int e = tid + j * 256;
            int t = e >> 10;
            int r = (e >> 3) & 127;
            int c = (e & 7) * 8;
            int row = (t < 2 ? bm : bn) + r;
            const void* src = &srcs[t][(size_t)row * GK + k0 + c];
            uint32_t dst = sb + t * TILE_BYTES + SWZ128((uint32_t)(r * 128 + c * 2));
            cp_async16(dst, src);
        }
    };

    float c[2][8][4];
#pragma unroll
    for (int mt = 0; mt < 2; mt++)
#pragma unroll
        for (int nt = 0; nt < 8; nt++)
#pragma unroll
            for (int q = 0; q < 4; q++) c[mt][nt][q] = 0.f;

    const int mi = lane >> 3, rr = lane & 7;

    load_chunk(0, 0);          CP_COMMIT();
    load_chunk(GBK, 1);        CP_COMMIT();

    for (int i = 0; i < NCHUNK; i++) {
        CP_WAIT(1);
        __syncthreads();
        if (i + 2 < NCHUNK) load_chunk((i + 2) * GBK, (i + 2) % 3);
        CP_COMMIT();

        const uint32_t st   = tiles_u32 + (i % 3) * STAGE_BYTES;
        const uint32_t Ah_b = st;
        const uint32_t Al_b = st + TILE_BYTES;
        const uint32_t Wh_b = st + 2 * TILE_BYTES;
        const uint32_t Wl_b = st + 3 * TILE_BYTES;

#pragma unroll
        for (int k16 = 0; k16 < 4; k16++) {
            const int kb = k16 * 16;
            uint32_t ah[2][4], al[2][4], bh[4][4], bl[4][4];
#pragma unroll
            for (int mt = 0; mt < 2; mt++) {
                const int m = wm + mt * 16 + (mi & 1) * 8 + rr;
                const int k = kb + (mi >> 1) * 8;
                const uint32_t off = SWZ128((uint32_t)(m * 128 + k * 2));
                ldsm4(Ah_b + off, ah[mt]);
                ldsm4(Al_b + off, al[mt]);
            }
#pragma unroll
            for (int np = 0; np < 4; np++) {
                const int n = wn + np * 16 + (mi >> 1) * 8 + rr;
                const int k = kb + (mi & 1) * 8;
                const uint32_t off = SWZ128((uint32_t)(n * 128 + k * 2));
                ldsm4(Wh_b + off, bh[np]);
                ldsm4(Wl_b + off, bl[np]);
            }
#pragma unroll
            for (int mt = 0; mt < 2; mt++)
#pragma unroll
                for (int nt = 0; nt < 8; nt++) {
                    const uint32_t* bhp = &bh[nt >> 1][(nt & 1) * 2];
                    const uint32_t* blp = &bl[nt >> 1][(nt & 1) * 2];
                    mma_bf16(c[mt][nt], ah[mt], bhp);
                    mma_bf16(c[mt][nt], ah[mt], blp);
                    mma_bf16(c[mt][nt], al[mt], bhp);
                }
        }
    }

#pragma unroll
    for (int mt = 0; mt < 2; mt++) {
        const int row0 = bm + wm + mt * 16 + (lane >> 2);
#pragma unroll
        for (int nt = 0; nt < 8; nt++) {
            const int col = bn + wn + nt * 8 + (lane & 3) * 2;
            const float b0 = bias[col], b1 = bias[col + 1];
            float2 v0 = make_float2(c[mt][nt][0] + b0, c[mt][nt][1] + b1);
            float2 v1 = make_float2(c[mt][nt][2] + b0, c[mt][nt][3] + b1);
            *(float2*)&C[(size_t)row0 * Ndim + col]       = v0;
            *(float2*)&C[(size_t)(row0 + 8) * Ndim + col] = v1;
        }
    }
}

// ======================= RoPE + split =====================================
__global__ __launch_bounds__(256) void rope_split_cvt(
    const float* __restrict__ cosb, const float* __restrict__ sinb,
    const float* __restrict__ QKV,
    __nv_bfloat16* __restrict__ qh, __nv_bfloat16* __restrict__ ql,
    __nv_bfloat16* __restrict__ kh, __nv_bfloat16* __restrict__ kl,
    __half* __restrict__ vh, __half* __restrict__ vl)
{
    const int tok = blockIdx.x;
    const int tid = threadIdx.x;
    const float* c = cosb + (size_t)tok * HD;
    const float* s = sinb + (size_t)tok * HD;
    const float* Qr  = QKV + (size_t)tok * QKVD;
    const float* KVr = Qr + D;

    for (int p = tid; p < H * 64; p += 256) {
        const int h = p >> 6, d = p & 63;
        const size_t ob = (size_t)tok * D + h * HD;
        const float a = Qr[h * HD + d], b2 = Qr[h * HD + d + 64];
        const float e0 = (a  * c[d]      - b2 * s[d])      * SCALE;
        const float e1 = (b2 * c[d + 64] + a  * s[d + 64]) * SCALE;
        const float h0 = bf16_round(e0), h1 = bf16_round(e1);
        qh[ob + d]      = __float2bfloat16(h0);
        qh[ob + d + 64] = __float2bfloat16(h1);
        ql[ob + d]      = __float2bfloat16(e0 - h0);
        ql[ob + d + 64] = __float2bfloat16(e1 - h1);
    }
    for (int p = tid; p < HKV * 64; p += 256) {
        const int h = p >> 6, d = p & 63;
        const size_t ob = (size_t)tok * KDIM + h * HD;
        const float a = KVr[h * HD + d], b2 = KVr[h * HD + d + 64];
        const float e0 = a  * c[d]      - b2 * s[d];
        const float e1 = b2 * c[d + 64] + a  * s[d + 64];
        const float h0 = bf16_round(e0), h1 = bf16_round(e1);
        kh[ob + d]      = __float2bfloat16(h0);
        kh[ob + d + 64] = __float2bfloat16(h1);
        kl[ob + d]      = __float2bfloat16(e0 - h0);
        kl[ob + d + 64] = __float2bfloat16(e1 - h1);
    }
    for (int e = tid; e < KDIM; e += 256) {
        const float v = KVr[KDIM + e];
        const __half h0 = __float2half_rn(v);
        vh[(size_t)tok * KDIM + e] = h0;
        vl[(size_t)tok * KDIM + e] = __float2half_rn(v - __half2float(h0));
    }
}

// ======================= flash attention (bf16x3 QK, fp16x2 PV) ===========
#define FBM 128
#define FBN 64
#define KP  136
#define KT_BYTES (FBN * KP * 2)       // 17408
#define FSTG (4 * KT_BYTES)           // Kh,Kl (bf16) + Vh,Vl (fp16)

__global__ __launch_bounds__(256, 1) void flash_mma(
    const __nv_bfloat16* __restrict__ Qh, const __nv_bfloat16* __restrict__ Ql,
    const __nv_bfloat16* __restrict__ Kh, const __nv_bfloat16* __restrict__ Kl,
    const __half* __restrict__ Vh, const __half* __restrict__ Vl,
    __nv_bfloat16* __restrict__ Ah, __nv_bfloat16* __restrict__ Al)
{
    extern __shared__ char smem_raw[];
    const uint32_t smem = smem_u32(smem_raw);

    const int tid  = threadIdx.x;
    const int w    = tid >> 5;
    const int lane = tid & 31;
    const int qblk = gridDim.x - 1 - blockIdx.x;   // longest-first schedule
    const int m0   = qblk * FBM;
    const int bh   = blockIdx.y;
    const int b    = bh / H;
    const int h    = bh % H;
    const int kvh  = h / GROUPS;

    const int rowg0 = m0 + w * 16 + (lane >> 2);
    const int rowg1 = rowg0 + 8;

    uint32_t qh[8][4], ql[8][4];
    {
        const size_t base0 = ((size_t)(b * L + rowg0) * H + h) * HD;
        const size_t base1 = base0 + (size_t)8 * H * HD;
#pragma unroll
        for (int j = 0; j < 8; j++) {
            const int c0 = j * 16 + (lane & 3) * 2;
            qh[j][0] = *(const uint32_t*)&Qh[base0 + c0];
            qh[j][1] = *(const uint32_t*)&Qh[base1 + c0];
            qh[j][2] = *(const uint32_t*)&Qh[base0 + c0 + 8];
            qh[j][3] = *(const uint32_t*)&Qh[base1 + c0 + 8];
            ql[j][0] = *(const uint32_t*)&Ql[base0 + c0];
            ql[j][1] = *(const uint32_t*)&Ql[base1 + c0];
            ql[j][2] = *(const uint32_t*)&Ql[base0 + c0 + 8];
            ql[j][3] = *(const uint32_t*)&Ql[base1 + c0 + 8];
        }
    }

    const void* kvsrc[4] = {Kh, Kl, Vh, Vl};
    auto load_kv = [&](int t, int s) {
        const int n0 = t * FBN;
        const uint32_t sb = smem + s * FSTG;
#pragma unroll
        for (int jj = 0; jj < 16; jj++) {
            int e = tid + jj * 256;
            int buf = e >> 10;
            int r   = (e >> 4) & 63;
            int ch  = e & 15;
            const size_t el = ((size_t)(b * L + n0 + r) * HKV + kvh) * HD + ch * 8;
            const void* src = (const char*)kvsrc[buf] + el * 2;
            uint32_t dst = sb + buf * KT_BYTES + (uint32_t)(r * KP + ch * 8) * 2;
            cp_async16(dst, src);
        }
    };

    float o[16][4];
#pragma unroll
    for (int nt = 0; nt < 16; nt++)
#pragma unroll
        for (int q = 0; q < 4; q++) o[nt][q] = 0.f;
    float mrow0 = -1e30f, mrow1 = -1e30f, lrow0 = 0.f, lrow1 = 0.f;

    const int ntiles = m0 / FBN + 2;
    load_kv(0, 0);
    CP_COMMIT();

    const int rlane = lane & 7;
    const int khalf = (lane >> 3) & 1;
    const int npair = lane >> 4;

    for (int t = 0; t < ntiles; t++) {
        CP_WAIT(0);
        __syncthreads();
        if (t + 1 < ntiles) load_kv(t + 1, (t + 1) & 1);
        CP_COMMIT();

        const int n0 = t * FBN;
        if (n0 > m0 + w * 16 + 15) continue;

        const uint32_t st  = smem + (t & 1) * FSTG;
        const uint32_t Khs = st;
        const uint32_t Kls = st + KT_BYTES;
        const uint32_t Vhs = st + 2 * KT_BYTES;
        const uint32_t Vls = st + 3 * KT_BYTES;

        float s8[8][4];
#pragma unroll
        for (int nt = 0; nt < 8; nt++)
#pragma unroll
            for (int q = 0; q < 4; q++) s8[nt][q] = 0.f;

#pragma unroll
        for (int j = 0; j < 8; j++) {
#pragma unroll
            for (int nt = 0; nt < 8; nt += 2) {
                uint32_t kb4[4], kl4[4];
                const uint32_t a = (uint32_t)(((nt + npair) * 8 + rlane) * KP
                                              + j * 16 + khalf * 8) * 2;
                ldsm4(Khs + a, kb4);
                ldsm4(Kls + a, kl4);
                mma_bf16(s8[nt],     qh[j], kb4);
                mma_bf16(s8[nt],     qh[j], kl4);
                mma_bf16(s8[nt],     ql[j], kb4);
                mma_bf16(s8[nt + 1], qh[j], kb4 + 2);
                mma_bf16(s8[nt + 1], qh[j], kl4 + 2);
                mma_bf16(s8[nt + 1], ql[j], kb4 + 2);
            }
        }

        if (t >= ntiles - 2) {
            const int colc = n0 + (lane & 3) * 2;
#pragma unroll
            for (int nt = 0; nt < 8; nt++) {
                const int cg = colc + nt * 8;
                if (cg     > rowg0) s8[nt][0] = -1e30f;
                if (cg + 1 > rowg0) s8[nt][1] = -1e30f;
                if (cg     > rowg1) s8[nt][2] = -1e30f;
                if (cg + 1 > rowg1) s8[nt][3] = -1e30f;
            }
        }

        float mx0 = -1e30f, mx1 = -1e30f;
#pragma unroll
        for (int nt = 0; nt < 8; nt++) {
            mx0 = fmaxf(mx0, fmaxf(s8[nt][0], s8[nt][1]));
            mx1 = fmaxf(mx1, fmaxf(s8[nt][2], s8[nt][3]));
        }
        mx0 = fmaxf(mx0, __shfl_xor_sync(0xffffffffu, mx0, 1));
        mx0 = fmaxf(mx0, __shfl_xor_sync(0xffffffffu, mx0, 2));
        mx1 = fmaxf(mx1, __shfl_xor_sync(0xffffffffu, mx1, 1));
        mx1 = fmaxf(mx1, __shfl_xor_sync(0xffffffffu, mx1, 2));

        const float mn0 = fmaxf(mrow0, mx0);
        const float mn1 = fmaxf(mrow1, mx1);
        const float alpha0 = __expf(mrow0 - mn0);
        const float alpha1 = __expf(mrow1 - mn1);

        float sum0 = 0.f, sum1 = 0.f;
#pragma unroll
        for (int nt = 0; nt < 8; nt++) {
            s8[nt][0] = __expf(s8[nt][0] - mn0);
            s8[nt][1] = __expf(s8[nt][1] - mn0);
            s8[nt][2] = __expf(s8[nt][2] - mn1);
            s8[nt][3] = __expf(s8[nt][3] - mn1);
            sum0 += s8[nt][0] + s8[nt][1];
            sum1 += s8[nt][2] + s8[nt][3];
        }
        sum0 += __shfl_xor_sync(0xffffffffu, sum0, 1);
        sum0 += __shfl_xor_sync(0xffffffffu, sum0, 2);
        sum1 += __shfl_xor_sync(0xffffffffu, sum1, 1);
        sum1 += __shfl_xor_sync(0xffffffffu, sum1, 2);

        lrow0 = lrow0 * alpha0 + sum0;
        lrow1 = lrow1 * alpha1 + sum1;
        mrow0 = mn0; mrow1 = mn1;

#pragma unroll
        for (int nt = 0; nt < 16; nt++) {
            o[nt][0] *= alpha0; o[nt][1] *= alpha0;
            o[nt][2] *= alpha1; o[nt][3] *= alpha1;
        }

        // ---- P·V in fp16: P single-precision fp16, V hi/lo (2 mma) ----
#pragma unroll
        for (int kt = 0; kt < 4; kt++) {
            uint32_t ph4[4];
            {
                const float* p0 = s8[2 * kt];
                const float* p1 = s8[2 * kt + 1];
                ph4[0] = pack_f16x2(p0[0], p0[1]);
                ph4[1] = pack_f16x2(p0[2], p0[3]);
                ph4[2] = pack_f16x2(p1[0], p1[1]);
                ph4[3] = pack_f16x2(p1[2], p1[3]);
            }
#pragma unroll
            for (int nt = 0; nt < 16; nt += 2) {
                uint32_t vh4[4], vl4[4];
                const uint32_t a = (uint32_t)((kt * 16 + khalf * 8 + rlane) * KP
                                              + (nt + npair) * 8) * 2;
                ldsm4t(Vhs + a, vh4);
                ldsm4t(Vls + a, vl4);
                mma_f16(o[nt],     ph4, vh4);
                mma_f16(o[nt],     ph4, vl4);
                mma_f16(o[nt + 1], ph4, vh4 + 2);
                mma_f16(o[nt + 1], ph4, vl4 + 2);
            }
        }
    }

    const float inv0 = 1.f / lrow0;
    const float inv1 = 1.f / lrow1;
    const size_t base0 = ((size_t)(b * L + rowg0) * H + h) * HD;
    const size_t base1 = base0 + (size_t)8 * H * HD;
#pragma unroll
    for (int nt = 0; nt < 16; nt++) {
        const int col = nt * 8 + (lane & 3) * 2;
        const float f0 = o[nt][0] * inv0, f1 = o[nt][1] * inv0;
        const float f2 = o[nt][2] * inv1, f3 = o[nt][3] * inv1;
        const float h0 = bf16_round(f0), h1 = bf16_round(f1);
        const float h2 = bf16_round(f2), h3 = bf16_round(f3);
        *(uint32_t*)&Ah[base0 + col] = pack_bf16x2(f0, f1);
        *(uint32_t*)&Ah[base1 + col] = pack_bf16x2(f2, f3);
        *(uint32_t*)&Al[base0 + col] = pack_bf16x2(f0 - h0, f1 - h1);
        *(uint32_t*)&Al[base1 + col] = pack_bf16x2(f2 - h2, f3 - h3);
    }
}

// ===========================================================================
extern "C" void kernel_launch(void* const* d_in, const int* in_sizes, int n_in,
                              void* d_out, int out_size)
{
    (void)in_sizes; (void)n_in; (void)out_size;
    const float* x    = (const float*)d_in[0];
    const float* cosb = (const float*)d_in[1];
    const float* sinb = (const float*)d_in[2];
    const float* Wq   = (const float*)d_in[3];
    const float* bq   = (const float*)d_in[4];
    const float* Wkv  = (const float*)d_in[5];
    const float* bkv  = (const float*)d_in[6];
    const float* Wo   = (const float*)d_in[7];
    const float* bo   = (const float*)d_in[8];
    float* out = (float*)d_out;

    float *QKVb, *bqkv;
    __nv_bfloat16 *xh, *xl, *wch, *wcl, *woh, *wol;
    __nv_bfloat16 *qh, *ql, *kh, *kl, *ah, *al;
    __half *vh, *vl;
    cudaGetSymbolAddress((void**)&QKVb, g_QKV);
    cudaGetSymbolAddress((void**)&bqkv, g_bqkv);
    cudaGetSymbolAddress((void**)&xh,  g_xh);
    cudaGetSymbolAddress((void**)&xl,  g_xl);
    cudaGetSymbolAddress((void**)&wch, g_wch);
    cudaGetSymbolAddress((void**)&wcl, g_wcl);
    cudaGetSymbolAddress((void**)&woh, g_woh);
    cudaGetSymbolAddress((void**)&wol, g_wol);
    cudaGetSymbolAddress((void**)&qh,  g_qh);
    cudaGetSymbolAddress((void**)&ql,  g_ql);
    cudaGetSymbolAddress((void**)&kh,  g_kh);
    cudaGetSymbolAddress((void**)&kl,  g_kl);
    cudaGetSymbolAddress((void**)&vh,  g_vh);
    cudaGetSymbolAddress((void**)&vl,  g_vl);
    cudaGetSymbolAddress((void**)&ah,  g_ah);
    cudaGetSymbolAddress((void**)&al,  g_al);

    const int gemm_smem = 1024 + 3 * STAGE_BYTES;
    cudaFuncSetAttribute(gemm_bf16x3, cudaFuncAttributeMaxDynamicSharedMemorySize,
                         gemm_smem);
    const int fa_smem = 2 * FSTG;
    cudaFuncSetAttribute(flash_mma, cudaFuncAttributeMaxDynamicSharedMemorySize,
                         fa_smem);

    // one fused conversion: x + concat(Wq,Wkv) + Wo + concat bias
    cvt_all<<<(N4_TOT + 255) / 256, 256>>>(x, Wq, Wkv, Wo, bq, bkv,
                                           xh, xl, wch, wcl, woh, wol, bqkv);

    // fused Q|KV projection (N = 3072)
    gemm_bf16x3<<<dim3(QKVD / 128, M_TOK / 128), 256, gemm_smem>>>(
        xh, xl, wch, wcl, bqkv, QKVb, QKVD);

    // RoPE + split (Q/K -> bf16 hi/lo, V -> fp16 hi/lo)
    rope_split_cvt<<<M_TOK, 256>>>(cosb, sinb, QKVb, qh, ql, kh, kl, vh, vl);

    // tensor-core flash attention -> Ah/Al splits
    flash_mma<<<dim3(L / FBM, B * H), 256, fa_smem>>>(
        qh, ql, kh, kl, vh, vl, ah, al);

    // O projection
    gemm_bf16x3<<<dim3(D / 128, M_TOK / 128), 256, gemm_smem>>>(
        ah, al, woh, wol, bo, out, D);
}

// round 12
// speedup vs baseline: 1.0994x; 1.0367x over previous
#include <cuda_runtime.h>
#include <cuda_bf16.h>
#include <cuda_fp16.h>
#include <math.h>
#include <stdint.h>

#define B 2
#define L 2048
#define D 2048
#define H 16
#define HKV 4
#define HD 128
#define GROUPS (H / HKV)
#define M_TOK (B * L)          // 4096 tokens
#define KVDIM (2 * HKV * HD)   // 1024
#define KDIM  (HKV * HD)       // 512
#define QKVD (D + KVDIM)       // 3072
#define SCALE 0.08838834764831845f

// ---------------- scratch ---------------------------------------------------
__device__ float g_bqkv[QKVD];
__device__ __nv_bfloat16 g_xh[(size_t)M_TOK * D];
__device__ __nv_bfloat16 g_xl[(size_t)M_TOK * D];
__device__ __nv_bfloat16 g_wch[(size_t)QKVD * D];
__device__ __nv_bfloat16 g_wcl[(size_t)QKVD * D];
__device__ __nv_bfloat16 g_woh[(size_t)D * D];
__device__ __nv_bfloat16 g_wol[(size_t)D * D];
__device__ __nv_bfloat16 g_qh[(size_t)M_TOK * D];
__device__ __nv_bfloat16 g_ql[(size_t)M_TOK * D];
__device__ __nv_bfloat16 g_kh[(size_t)M_TOK * KDIM];
__device__ __nv_bfloat16 g_kl[(size_t)M_TOK * KDIM];
__device__ __half g_vh[(size_t)M_TOK * KDIM];
__device__ __nv_bfloat16 g_ah[(size_t)M_TOK * D];
__device__ __nv_bfloat16 g_al[(size_t)M_TOK * D];

// ======================= helpers ==========================================
__device__ __forceinline__ uint32_t smem_u32(const void* p) {
    uint32_t a;
    asm("{ .reg .u64 t; cvta.to.shared.u64 t, %1; cvt.u32.u64 %0, t; }"
        : "=r"(a) : "l"(p));
    return a;
}
#define SWZ128(off) ((off) ^ (((off) >> 3) & 0x70))

__device__ __forceinline__ void ldsm4(uint32_t addr, uint32_t* r) {
    asm volatile("ldmatrix.sync.aligned.m8n8.x4.shared.b16 {%0,%1,%2,%3}, [%4];"
                 : "=r"(r[0]), "=r"(r[1]), "=r"(r[2]), "=r"(r[3]) : "r"(addr));
}
__device__ __forceinline__ void ldsm4t(uint32_t addr, uint32_t* r) {
    asm volatile("ldmatrix.sync.aligned.m8n8.x4.trans.shared.b16 {%0,%1,%2,%3}, [%4];"
                 : "=r"(r[0]), "=r"(r[1]), "=r"(r[2]), "=r"(r[3]) : "r"(addr));
}
__device__ __forceinline__ void mma_bf16(float* c, const uint32_t* a,
                                         const uint32_t* b) {
    asm volatile(
        "mma.sync.aligned.m16n8k16.row.col.f32.bf16.bf16.f32 "
        "{%0,%1,%2,%3}, {%4,%5,%6,%7}, {%8,%9}, {%0,%1,%2,%3};"
        : "+f"(c[0]), "+f"(c[1]), "+f"(c[2]), "+f"(c[3])
        : "r"(a[0]), "r"(a[1]), "r"(a[2]), "r"(a[3]), "r"(b[0]), "r"(b[1]));
}
__device__ __forceinline__ void mma_f16(float* c, const uint32_t* a,
                                        const uint32_t* b) {
    asm volatile(
        "mma.sync.aligned.m16n8k16.row.col.f32.f16.f16.f32 "
        "{%0,%1,%2,%3}, {%4,%5,%6,%7}, {%8,%9}, {%0,%1,%2,%3};"
        : "+f"(c[0]), "+f"(c[1]), "+f"(c[2]), "+f"(c[3])
        : "r"(a[0]), "r"(a[1]), "r"(a[2]), "r"(a[3]), "r"(b[0]), "r"(b[1]));
}
__device__ __forceinline__ void cp_async16(uint32_t dst, const void* src) {
    asm volatile("cp.async.cg.shared.global [%0], [%1], 16;"
                 :: "r"(dst), "l"(src));
}
#define CP_COMMIT() asm volatile("cp.async.commit_group;" ::: "memory")
#define CP_WAIT(N)  asm volatile("cp.async.wait_group %0;" :: "n"(N) : "memory")

__device__ __forceinline__ uint32_t pack_bf16x2(float lo, float hi) {
    uint32_t r;
    asm("cvt.rn.bf16x2.f32 %0, %1, %2;" : "=r"(r) : "f"(hi), "f"(lo));
    return r;
}
__device__ __forceinline__ uint32_t pack_f16x2(float lo, float hi) {
    uint32_t r;
    asm("cvt.rn.f16x2.f32 %0, %1, %2;" : "=r"(r) : "f"(hi), "f"(lo));
    return r;
}
__device__ __forceinline__ float bf16_round(float x) {
    return __bfloat162float(__float2bfloat16(x));
}

// ======================= fused hi/lo split (x + weights + bias) ===========
#define N4_X   ((M_TOK * D) / 4)
#define N4_WQ  ((D * D) / 4)
#define N4_WKV ((KVDIM * D) / 4)
#define N4_WO  ((D * D) / 4)
#define N4_BIA (QKVD / 4)
#define N4_TOT (N4_X + N4_WQ + N4_WKV + N4_WO + N4_BIA)

__device__ __forceinline__ void split4(const float* __restrict__ src,
                                       __nv_bfloat16* __restrict__ hi,
                                       __nv_bfloat16* __restrict__ lo, int i) {
    float4 v = ((const float4*)src)[i];
    float h0 = bf16_round(v.x), h1 = bf16_round(v.y);
    float h2 = bf16_round(v.z), h3 = bf16_round(v.w);
    uint32_t* hp = (uint32_t*)hi;
    uint32_t* lp = (uint32_t*)lo;
    hp[2 * i]     = pack_bf16x2(v.x, v.y);
    hp[2 * i + 1] = pack_bf16x2(v.z, v.w);
    lp[2 * i]     = pack_bf16x2(v.x - h0, v.y - h1);
    lp[2 * i + 1] = pack_bf16x2(v.z - h2, v.w - h3);
}

__global__ __launch_bounds__(256) void cvt_all(
    const float* __restrict__ x,  const float* __restrict__ Wq,
    const float* __restrict__ Wkv, const float* __restrict__ Wo,
    const float* __restrict__ bq,  const float* __restrict__ bkv,
    __nv_bfloat16* __restrict__ xh,  __nv_bfloat16* __restrict__ xl,
    __nv_bfloat16* __restrict__ wch, __nv_bfloat16* __restrict__ wcl,
    __nv_bfloat16* __restrict__ woh, __nv_bfloat16* __restrict__ wol,
    float* __restrict__ bqkv)
{
    int i = blockIdx.x * blockDim.x + threadIdx.x;
    if (i < N4_X) { split4(x, xh, xl, i); return; }
    i -= N4_X;
    if (i < N4_WQ) { split4(Wq, wch, wcl, i); return; }
    i -= N4_WQ;
    if (i < N4_WKV) { split4(Wkv, wch + (size_t)D * D, wcl + (size_t)D * D, i); return; }
    i -= N4_WKV;
    if (i < N4_WO) { split4(Wo, woh, wol, i); return; }
    i -= N4_WO;
    if (i < N4_BIA) {
        float4 v = (i < D / 4) ? ((const float4*)bq)[i]
                               : ((const float4*)bkv)[i - D / 4];
        ((float4*)bqkv)[i] = v;
    }
}

// ======================= mma.sync bf16x3 GEMM =============================
// 128x128 CTA tile, warp grid 8(M)x1(N): warp tile 16x128 (full head per warp)
// MODE 0: QKV projection epilogue = bias + RoPE + hi/lo split -> q/k/v bufs
// MODE 1: O projection epilogue   = bias + fp32 store
#define GK 2048
#define GBK 64
#define NCHUNK (GK / GBK)           // 32
#define TILE_BYTES 16384
#define STAGE_BYTES (4 * TILE_BYTES)

template <int MODE>
__global__ __launch_bounds__(256, 1) void gemm_bf16x3(
    const __nv_bfloat16* __restrict__ Ah, const __nv_bfloat16* __restrict__ Al,
    const __nv_bfloat16* __restrict__ Wh, const __nv_bfloat16* __restrict__ Wl,
    const float* __restrict__ bias, float* __restrict__ C,
    const float* __restrict__ cosb, const float* __restrict__ sinb,
    __nv_bfloat16* __restrict__ qh, __nv_bfloat16* __restrict__ ql,
    __nv_bfloat16* __restrict__ kh, __nv_bfloat16* __restrict__ kl,
    __half* __restrict__ vh)
{
    extern __shared__ char smem_raw[];
    char* tiles = (char*)(((uintptr_t)smem_raw + 1023) & ~(uintptr_t)1023);
    const uint32_t tiles_u32 = smem_u32(tiles);

    const int tid  = threadIdx.x;
    const int wid  = tid >> 5;
    const int lane = tid & 31;
    const int bm = blockIdx.y * 128;
    const int bn = blockIdx.x * 128;
    const int wm = wid * 16;

    const __nv_bfloat16* srcs[4] = {Ah, Al, Wh, Wl};

    auto load_chunk = [&](int k0, int s) {
        const uint32_t sb = tiles_u32 + s * STAGE_BYTES;
#pragma unroll
        for (int j = 0; j < 16; j++) {
            int e = tid + j * 256;
            int t = e >> 10;
            int r = (e >> 3) & 127;
            int c = (e & 7) * 8;
            int row = (t < 2 ? bm : bn) + r;
            const void* src = &srcs[t][(size_t)row * GK + k0 + c];
            uint32_t dst = sb + t * TILE_BYTES + SWZ128((uint32_t)(r * 128 + c * 2));
            cp_async16(dst, src);
        }
    };

    float c[16][4];
#pragma unroll
    for (int nt = 0; nt < 16; nt++)
#pragma unroll
        for (int q = 0; q < 4; q++) c[nt][q] = 0.f;

    const int mi = lane >> 3, rr = lane & 7;

    load_chunk(0, 0);          CP_COMMIT();
    load_chunk(GBK, 1);        CP_COMMIT();

    for (int i = 0; i < NCHUNK; i++) {
        CP_WAIT(1);
        __syncthreads();
        if (i + 2 < NCHUNK) load_chunk((i + 2) * GBK, (i + 2) % 3);
        CP_COMMIT();

        const uint32_t st   = tiles_u32 + (i % 3) * STAGE_BYTES;
        const uint32_t Ah_b = st;
        const uint32_t Al_b = st + TILE_BYTES;
        const uint32_t Wh_b = st + 2 * TILE_BYTES;
        const uint32_t Wl_b = st + 3 * TILE_BYTES;

#pragma unroll
        for (int k16 = 0; k16 < 4; k16++) {
            const int kb = k16 * 16;
            uint32_t ah[4], al[4];
            {
                const int m = wm + (mi & 1) * 8 + rr;
                const int k = kb + (mi >> 1) * 8;
                const uint32_t off = SWZ128((uint32_t)(m * 128 + k * 2));
                ldsm4(Ah_b + off, ah);
                ldsm4(Al_b + off, al);
            }
#pragma unroll
            for (int np = 0; np < 8; np++) {
                uint32_t bh4[4], bl4[4];
                const int n = np * 16 + (mi >> 1) * 8 + rr;
                const int k = kb + (mi & 1) * 8;
                const uint32_t off = SWZ128((uint32_t)(n * 128 + k * 2));
                ldsm4(Wh_b + off, bh4);
                ldsm4(Wl_b + off, bl4);
#pragma unroll
                for (int half = 0; half < 2; half++) {
                    float* cc = c[np * 2 + half];
                    mma_bf16(cc, ah, bh4 + half * 2);
                    mma_bf16(cc, ah, bl4 + half * 2);
                    mma_bf16(cc, al, bh4 + half * 2);
                }
            }
        }
    }

    // ---- epilogue ----
    const int tok0 = bm + wm + (lane >> 2);
    const int tok1 = tok0 + 8;
    const int cl2  = (lane & 3) * 2;

    // bias add
#pragma unroll
    for (int nt = 0; nt < 16; nt++) {
        const float b0 = bias[bn + nt * 8 + cl2];
        const float b1 = bias[bn + nt * 8 + cl2 + 1];
        c[nt][0] += b0; c[nt][1] += b1;
        c[nt][2] += b0; c[nt][3] += b1;
    }

    if (MODE == 1) {
#pragma unroll
        for (int nt = 0; nt < 16; nt++) {
            const int col = bn + nt * 8 + cl2;
            *(float2*)&C[(size_t)tok0 * D + col] = make_float2(c[nt][0], c[nt][1]);
            *(float2*)&C[(size_t)tok1 * D + col] = make_float2(c[nt][2], c[nt][3]);
        }
        return;
    }

    // MODE 0: QKV epilogue
    if (bn < D + KDIM) {
        // Q or K head: apply RoPE on pairs (nt, nt+8)
        const bool isQ = (bn < D);
        const float sc = isQ ? SCALE : 1.0f;
        __nv_bfloat16* dh = isQ ? qh : kh;
        __nv_bfloat16* dl = isQ ? ql : kl;
        const int hbase = isQ ? bn : (bn - D);        // head offset in dest row
        const int rowstr = isQ ? D : KDIM;
#pragma unroll
        for (int nt = 0; nt < 8; nt++) {
            const int d = nt * 8 + cl2;               // 0..62 range +
            const float2 c0a = *(const float2*)&cosb[(size_t)tok0 * HD + d];
            const float2 s0a = *(const float2*)&sinb[(size_t)tok0 * HD + d];
            const float2 c0b = *(const float2*)&cosb[(size_t)tok0 * HD + d + 64];
            const float2 s0b = *(const float2*)&sinb[(size_t)tok0 * HD + d + 64];
            const float2 c1a = *(const float2*)&cosb[(size_t)tok1 * HD + d];
            const float2 s1a = *(const float2*)&sinb[(size_t)tok1 * HD + d];
            const float2 c1b = *(const float2*)&cosb[(size_t)tok1 * HD + d + 64];
            const float2 s1b = *(const float2*)&sinb[(size_t)tok1 * HD + d + 64];

            // row tok0
            float e0x = (c[nt][0] * c0a.x - c[nt + 8][0] * s0a.x) * sc;
            float e0y = (c[nt][1] * c0a.y - c[nt + 8][1] * s0a.y) * sc;
            float e1x = (c[nt + 8][0] * c0b.x + c[nt][0] * s0b.x) * sc;
            float e1y = (c[nt + 8][1] * c0b.y + c[nt][1] * s0b.y) * sc;
            // row tok1
            float f0x = (c[nt][2] * c1a.x - c[nt + 8][2] * s1a.x) * sc;
            float f0y = (c[nt][3] * c1a.y - c[nt + 8][3] * s1a.y) * sc;
            float f1x = (c[nt + 8][2] * c1b.x + c[nt][2] * s1b.x) * sc;
            float f1y = (c[nt + 8][3] * c1b.y + c[nt][3] * s1b.y) * sc;

            const size_t o0 = (size_t)tok0 * rowstr + hbase + d;
            const size_t o1 = (size_t)tok1 * rowstr + hbase + d;
            float h0, h1;
            h0 = bf16_round(e0x); h1 = bf16_round(e0y);
            *(uint32_t*)&dh[o0]      = pack_bf16x2(e0x, e0y);
            *(uint32_t*)&dl[o0]      = pack_bf16x2(e0x - h0, e0y - h1);
            h0 = bf16_round(e1x); h1 = bf16_round(e1y);
            *(uint32_t*)&dh[o0 + 64] = pack_bf16x2(e1x, e1y);
            *(uint32_t*)&dl[o0 + 64] = pack_bf16x2(e1x - h0, e1y - h1);
            h0 = bf16_round(f0x); h1 = bf16_round(f0y);
            *(uint32_t*)&dh[o1]      = pack_bf16x2(f0x, f0y);
            *(uint32_t*)&dl[o1]      = pack_bf16x2(f0x - h0, f0y - h1);
            h0 = bf16_round(f1x); h1 = bf16_round(f1y);
            *(uint32_t*)&dh[o1 + 64] = pack_bf16x2(f1x, f1y);
            *(uint32_t*)&dl[o1 + 64] = pack_bf16x2(f1x - h0, f1y - h1);
        }
    } else {
        // V head: plain fp16 store
        const int hbase = bn - D - KDIM;
#pragma unroll
        for (int nt = 0; nt < 16; nt++) {
            const int coln = nt * 8 + cl2;
            *(uint32_t*)&vh[(size_t)tok0 * KDIM + hbase + coln] =
                pack_f16x2(c[nt][0], c[nt][1]);
            *(uint32_t*)&vh[(size_t)tok1 * KDIM + hbase + coln] =
                pack_f16x2(c[nt][2], c[nt][3]);
        }
    }
}

// ======================= flash attention (bf16x3 QK, fp16 PV) =============
#define FBM 128
#define FBN 64
#define KP  136
#define KT_BYTES (FBN * KP * 2)       // 17408
#define FSTG (3 * KT_BYTES)           // Kh,Kl (bf16) + Vh (fp16)

__global__ __launch_bounds__(256, 1) void flash_mma(
    const __nv_bfloat16* __restrict__ Qh, const __nv_bfloat16* __restrict__ Ql,
    const __nv_bfloat16* __restrict__ Kh, const __nv_bfloat16* __restrict__ Kl,
    const __half* __restrict__ Vh,
    __nv_bfloat16* __restrict__ Ah, __nv_bfloat16* __restrict__ Al)
{
    extern __shared__ char smem_raw[];
    const uint32_t smem = smem_u32(smem_raw);

    const int tid  = threadIdx.x;
    const int w    = tid >> 5;
    const int lane = tid & 31;
    const int qblk = gridDim.x - 1 - blockIdx.x;   // longest-first
    const int m0   = qblk * FBM;
    const int bh   = blockIdx.y;
    const int b    = bh / H;
    const int h    = bh % H;
    const int kvh  = h / GROUPS;

    const int rowg0 = m0 + w * 16 + (lane >> 2);
    const int rowg1 = rowg0 + 8;

    uint32_t qh[8][4], ql[8][4];
    {
        const size_t base0 = ((size_t)(b * L + rowg0) * H + h) * HD;
        const size_t base1 = base0 + (size_t)8 * H * HD;
#pragma unroll
        for (int j = 0; j < 8; j++) {
            const int c0 = j * 16 + (lane & 3) * 2;
            qh[j][0] = *(const uint32_t*)&Qh[base0 + c0];
            qh[j][1] = *(const uint32_t*)&Qh[base1 + c0];
            qh[j][2] = *(const uint32_t*)&Qh[base0 + c0 + 8];
            qh[j][3] = *(const uint32_t*)&Qh[base1 + c0 + 8];
            ql[j][0] = *(const uint32_t*)&Ql[base0 + c0];
            ql[j][1] = *(const uint32_t*)&Ql[base1 + c0];
            ql[j][2] = *(const uint32_t*)&Ql[base0 + c0 + 8];
            ql[j][3] = *(const uint32_t*)&Ql[base1 + c0 + 8];
        }
    }

    const void* kvsrc[3] = {Kh, Kl, Vh};
    auto load_kv = [&](int t, int s) {
        const int n0 = t * FBN;
        const uint32_t sb = smem + s * FSTG;
#pragma unroll
        for (int jj = 0; jj < 12; jj++) {
            int e = tid + jj * 256;
            int buf = e >> 10;
            int r   = (e >> 4) & 63;
            int ch  = e & 15;
            const size_t el = ((size_t)(b * L + n0 + r) * HKV + kvh) * HD + ch * 8;
            const void* src = (const char*)kvsrc[buf] + el * 2;
            uint32_t dst = sb + buf * KT_BYTES + (uint32_t)(r * KP + ch * 8) * 2;
            cp_async16(dst, src);
        }
    };

    float o[16][4];
#pragma unroll
    for (int nt = 0; nt < 16; nt++)
#pragma unroll
        for (int q = 0; q < 4; q++) o[nt][q] = 0.f;
    float mrow0 = -1e30f, mrow1 = -1e30f, lrow0 = 0.f, lrow1 = 0.f;

    const int ntiles = m0 / FBN + 2;
    load_kv(0, 0);
    CP_COMMIT();

    const int rlane = lane & 7;
    const int khalf = (lane >> 3) & 1;
    const int npair = lane >> 4;

    for (int t = 0; t < ntiles; t++) {
        CP_WAIT(0);
        __syncthreads();
        if (t + 1 < ntiles) load_kv(t + 1, (t + 1) & 1);
        CP_COMMIT();

        const int n0 = t * FBN;
        if (n0 > m0 + w * 16 + 15) continue;

        const uint32_t st  = smem + (t & 1) * FSTG;
        const uint32_t Khs = st;
        const uint32_t Kls = st + KT_BYTES;
        const uint32_t Vhs = st + 2 * KT_BYTES;

        float s8[8][4];
#pragma unroll
        for (int nt = 0; nt < 8; nt++)
#pragma unroll
            for (int q = 0; q < 4; q++) s8[nt][q] = 0.f;

#pragma unroll
        for (int j = 0; j < 8; j++) {
#pragma unroll
            for (int nt = 0; nt < 8; nt += 2) {
                uint32_t kb4[4], kl4[4];
                const uint32_t a = (uint32_t)(((nt + npair) * 8 + rlane) * KP
                                              + j * 16 + khalf * 8) * 2;
                ldsm4(Khs + a, kb4);
                ldsm4(Kls + a, kl4);
                mma_bf16(s8[nt],     qh[j], kb4);
                mma_bf16(s8[nt],     qh[j], kl4);
                mma_bf16(s8[nt],     ql[j], kb4);
                mma_bf16(s8[nt + 1], qh[j], kb4 + 2);
                mma_bf16(s8[nt + 1], qh[j], kl4 + 2);
                mma_bf16(s8[nt + 1], ql[j], kb4 + 2);
            }
        }

        if (t >= ntiles - 2) {
            const int colc = n0 + (lane & 3) * 2;
#pragma unroll
            for (int nt = 0; nt < 8; nt++) {
                const int cg = colc + nt * 8;
                if (cg     > rowg0) s8[nt][0] = -1e30f;
                if (cg + 1 > rowg0) s8[nt][1] = -1e30f;
                if (cg     > rowg1) s8[nt][2] = -1e30f;
                if (cg + 1 > rowg1) s8[nt][3] = -1e30f;
            }
        }

        float mx0 = -1e30f, mx1 = -1e30f;
#pragma unroll
        for (int nt = 0; nt < 8; nt++) {
            mx0 = fmaxf(mx0, fmaxf(s8[nt][0], s8[nt][1]));
            mx1 = fmaxf(mx1, fmaxf(s8[nt][2], s8[nt][3]));
        }
        mx0 = fmaxf(mx0, __shfl_xor_sync(0xffffffffu, mx0, 1));
        mx0 = fmaxf(mx0, __shfl_xor_sync(0xffffffffu, mx0, 2));
        mx1 = fmaxf(mx1, __shfl_xor_sync(0xffffffffu, mx1, 1));
        mx1 = fmaxf(mx1, __shfl_xor_sync(0xffffffffu, mx1, 2));

        const float mn0 = fmaxf(mrow0, mx0);
        const float mn1 = fmaxf(mrow1, mx1);
        const float alpha0 = __expf(mrow0 - mn0);
        const float alpha1 = __expf(mrow1 - mn1);

        float sum0 = 0.f, sum1 = 0.f;
#pragma unroll
        for (int nt = 0; nt < 8; nt++) {
            s8[nt][0] = __expf(s8[nt][0] - mn0);
            s8[nt][1] = __expf(s8[nt][1] - mn0);
            s8[nt][2] = __expf(s8[nt][2] - mn1);
            s8[nt][3] = __expf(s8[nt][3] - mn1);
            sum0 += s8[nt][0] + s8[nt][1];
            sum1 += s8[nt][2] + s8[nt][3];
        }
        sum0 += __shfl_xor_sync(0xffffffffu, sum0, 1);
        sum0 += __shfl_xor_sync(0xffffffffu, sum0, 2);
        sum1 += __shfl_xor_sync(0xffffffffu, sum1, 1);
        sum1 += __shfl_xor_sync(0xffffffffu, sum1, 2);

        lrow0 = lrow0 * alpha0 + sum0;
        lrow1 = lrow1 * alpha1 + sum1;
        mrow0 = mn0; mrow1 = mn1;

#pragma unroll
        for (int nt = 0; nt < 16; nt++) {
            o[nt][0] *= alpha0; o[nt][1] *= alpha0;
            o[nt][2] *= alpha1; o[nt][3] *= alpha1;
        }

        // ---- P·V: P fp16 single, V fp16 single ----
#pragma unroll
        for (int kt = 0; kt < 4; kt++) {
            uint32_t ph4[4];
            {
                const float* p0 = s8[2 * kt];
                const float* p1 = s8[2 * kt + 1];
                ph4[0] = pack_f16x2(p0[0], p0[1]);
                ph4[1] = pack_f16x2(p0[2], p0[3]);
                ph4[2] = pack_f16x2(p1[0], p1[1]);
                ph4[3] = pack_f16x2(p1[2], p1[3]);
            }
#pragma unroll
            for (int nt = 0; nt < 16; nt += 2) {
                uint32_t vh4[4];
                const uint32_t a = (uint32_t)((kt * 16 + khalf * 8 + rlane) * KP
                                              + (nt + npair) * 8) * 2;
                ldsm4t(Vhs + a, vh4);
                mma_f16(o[nt],     ph4, vh4);
                mma_f16(o[nt + 1], ph4, vh4 + 2);
            }
        }
    }

    const float inv0 = 1.f / lrow0;
    const float inv1 = 1.f / lrow1;
    const size_t base0 = ((size_t)(b * L + rowg0) * H + h) * HD;
    const size_t base1 = base0 + (size_t)8 * H * HD;
#pragma unroll
    for (int nt = 0; nt < 16; nt++) {
        const int col = nt * 8 + (lane & 3) * 2;
        const float f0 = o[nt][0] * inv0, f1 = o[nt][1] * inv0;
        const float f2 = o[nt][2] * inv1, f3 = o[nt][3] * inv1;
        const float h0 = bf16_round(f0), h1 = bf16_round(f1);
        const float h2 = bf16_round(f2), h3 = bf16_round(f3);
        *(uint32_t*)&Ah[base0 + col] = pack_bf16x2(f0, f1);
        *(uint32_t*)&Ah[base1 + col] = pack_bf16x2(f2, f3);
        *(uint32_t*)&Al[base0 + col] = pack_bf16x2(f0 - h0, f1 - h1);
        *(uint32_t*)&Al[base1 + col] = pack_bf16x2(f2 - h2, f3 - h3);
    }
}

// ===========================================================================
extern "C" void kernel_launch(void* const* d_in, const int* in_sizes, int n_in,
                              void* d_out, int out_size)
{
    (void)in_sizes; (void)n_in; (void)out_size;
    const float* x    = (const float*)d_in[0];
    const float* cosb = (const float*)d_in[1];
    const float* sinb = (const float*)d_in[2];
    const float* Wq   = (const float*)d_in[3];
    const float* bq   = (const float*)d_in[4];
    const float* Wkv  = (const float*)d_in[5];
    const float* bkv  = (const float*)d_in[6];
    const float* Wo   = (const float*)d_in[7];
    const float* bo   = (const float*)d_in[8];
    float* out = (float*)d_out;

    float *bqkv;
    __nv_bfloat16 *xh, *xl, *wch, *wcl, *woh, *wol;
    __nv_bfloat16 *qh, *ql, *kh, *kl, *ah, *al;
    __half *vh;
    cudaGetSymbolAddress((void**)&bqkv, g_bqkv);
    cudaGetSymbolAddress((void**)&xh,  g_xh);
    cudaGetSymbolAddress((void**)&xl,  g_xl);
    cudaGetSymbolAddress((void**)&wch, g_wch);
    cudaGetSymbolAddress((void**)&wcl, g_wcl);
    cudaGetSymbolAddress((void**)&woh, g_woh);
    cudaGetSymbolAddress((void**)&wol, g_wol);
    cudaGetSymbolAddress((void**)&qh,  g_qh);
    cudaGetSymbolAddress((void**)&ql,  g_ql);
    cudaGetSymbolAddress((void**)&kh,  g_kh);
    cudaGetSymbolAddress((void**)&kl,  g_kl);
    cudaGetSymbolAddress((void**)&vh,  g_vh);
    cudaGetSymbolAddress((void**)&ah,  g_ah);
    cudaGetSymbolAddress((void**)&al,  g_al);

    const int gemm_smem = 1024 + 3 * STAGE_BYTES;
    cudaFuncSetAttribute(gemm_bf16x3<0>, cudaFuncAttributeMaxDynamicSharedMemorySize,
                         gemm_smem);
    cudaFuncSetAttribute(gemm_bf16x3<1>, cudaFuncAttributeMaxDynamicSharedMemorySize,
                         gemm_smem);
    const int fa_smem = 2 * FSTG;
    cudaFuncSetAttribute(flash_mma, cudaFuncAttributeMaxDynamicSharedMemorySize,
                         fa_smem);

    // fused conversion: x + concat(Wq,Wkv) + Wo + concat bias
    cvt_all<<<(N4_TOT + 255) / 256, 256>>>(x, Wq, Wkv, Wo, bq, bkv,
                                           xh, xl, wch, wcl, woh, wol, bqkv);

    // fused QKV projection with RoPE+split epilogue
    gemm_bf16x3<0><<<dim3(QKVD / 128, M_TOK / 128), 256, gemm_smem>>>(
        xh, xl, wch, wcl, bqkv, nullptr, cosb, sinb, qh, ql, kh, kl, vh);

    // tensor-core flash attention -> Ah/Al splits
    flash_mma<<<dim3(L / FBM, B * H), 256, fa_smem>>>(
        qh, ql, kh, kl, vh, ah, al);

    // O projection
    gemm_bf16x3<1><<<dim3(D / 128, M_TOK / 128), 256, gemm_smem>>>(
        ah, al, woh, wol, bo, out, nullptr, nullptr,
        nullptr, nullptr, nullptr, nullptr, nullptr);
}

// round 13
// speedup vs baseline: 1.1072x; 1.0071x over previous
#include <cuda_runtime.h>
#include <cuda_bf16.h>
#include <cuda_fp16.h>
#include <math.h>
#include <stdint.h>

#define B 2
#define L 2048
#define D 2048
#define H 16
#define HKV 4
#define HD 128
#define GROUPS (H / HKV)
#define M_TOK (B * L)          // 4096 tokens
#define KVDIM (2 * HKV * HD)   // 1024
#define KDIM  (HKV * HD)       // 512
#define QKVD (D + KVDIM)       // 3072
#define SCALE 0.08838834764831845f

// ---------------- scratch ---------------------------------------------------
__device__ float g_bqkv[QKVD];
__device__ __nv_bfloat16 g_xh[(size_t)M_TOK * D];
__device__ __nv_bfloat16 g_xl[(size_t)M_TOK * D];
__device__ __nv_bfloat16 g_wch[(size_t)QKVD * D];
__device__ __nv_bfloat16 g_wcl[(size_t)QKVD * D];
__device__ __nv_bfloat16 g_woh[(size_t)D * D];
__device__ __nv_bfloat16 g_wol[(size_t)D * D];
__device__ __nv_bfloat16 g_qh[(size_t)M_TOK * D];
__device__ __nv_bfloat16 g_ql[(size_t)M_TOK * D];
__device__ __nv_bfloat16 g_kh[(size_t)M_TOK * KDIM];
__device__ __nv_bfloat16 g_kl[(size_t)M_TOK * KDIM];
__device__ __half g_vh[(size_t)M_TOK * KDIM];
__device__ __nv_bfloat16 g_ah[(size_t)M_TOK * D];
__device__ __nv_bfloat16 g_al[(size_t)M_TOK * D];

// ======================= helpers ==========================================
__device__ __forceinline__ uint32_t smem_u32(const void* p) {
    uint32_t a;
    asm("{ .reg .u64 t; cvta.to.shared.u64 t, %1; cvt.u32.u64 %0, t; }"
        : "=r"(a) : "l"(p));
    return a;
}
#define SWZ128(off) ((off) ^ (((off) >> 3) & 0x70))

__device__ __forceinline__ void ldsm4(uint32_t addr, uint32_t* r) {
    asm volatile("ldmatrix.sync.aligned.m8n8.x4.shared.b16 {%0,%1,%2,%3}, [%4];"
                 : "=r"(r[0]), "=r"(r[1]), "=r"(r[2]), "=r"(r[3]) : "r"(addr));
}
__device__ __forceinline__ void ldsm4t(uint32_t addr, uint32_t* r) {
    asm volatile("ldmatrix.sync.aligned.m8n8.x4.trans.shared.b16 {%0,%1,%2,%3}, [%4];"
                 : "=r"(r[0]), "=r"(r[1]), "=r"(r[2]), "=r"(r[3]) : "r"(addr));
}
__device__ __forceinline__ void mma_bf16(float* c, const uint32_t* a,
                                         const uint32_t* b) {
    asm volatile(
        "mma.sync.aligned.m16n8k16.row.col.f32.bf16.bf16.f32 "
        "{%0,%1,%2,%3}, {%4,%5,%6,%7}, {%8,%9}, {%0,%1,%2,%3};"
        : "+f"(c[0]), "+f"(c[1]), "+f"(c[2]), "+f"(c[3])
        : "r"(a[0]), "r"(a[1]), "r"(a[2]), "r"(a[3]), "r"(b[0]), "r"(b[1]));
}
__device__ __forceinline__ void mma_f16(float* c, const uint32_t* a,
                                        const uint32_t* b) {
    asm volatile(
        "mma.sync.aligned.m16n8k16.row.col.f32.f16.f16.f32 "
        "{%0,%1,%2,%3}, {%4,%5,%6,%7}, {%8,%9}, {%0,%1,%2,%3};"
        : "+f"(c[0]), "+f"(c[1]), "+f"(c[2]), "+f"(c[3])
        : "r"(a[0]), "r"(a[1]), "r"(a[2]), "r"(a[3]), "r"(b[0]), "r"(b[1]));
}
__device__ __forceinline__ void cp_async16(uint32_t dst, const void* src) {
    asm volatile("cp.async.cg.shared.global [%0], [%1], 16;"
                 :: "r"(dst), "l"(src));
}
#define CP_COMMIT() asm volatile("cp.async.commit_group;" ::: "memory")
#define CP_WAIT(N)  asm volatile("cp.async.wait_group %0;" :: "n"(N) : "memory")

__device__ __forceinline__ uint32_t pack_bf16x2(float lo, float hi) {
    uint32_t r;
    asm("cvt.rn.bf16x2.f32 %0, %1, %2;" : "=r"(r) : "f"(hi), "f"(lo));
    return r;
}
__device__ __forceinline__ uint32_t pack_f16x2(float lo, float hi) {
    uint32_t r;
    asm("cvt.rn.f16x2.f32 %0, %1, %2;" : "=r"(r) : "f"(hi), "f"(lo));
    return r;
}
__device__ __forceinline__ float bf16_round(float x) {
    return __bfloat162float(__float2bfloat16(x));
}

// ======================= fused hi/lo split (x + weights + bias) ===========
#define N4_X   ((M_TOK * D) / 4)
#define N4_WQ  ((D * D) / 4)
#define N4_WKV ((KVDIM * D) / 4)
#define N4_WO  ((D * D) / 4)
#define N4_BIA (QKVD / 4)
#define N4_TOT (N4_X + N4_WQ + N4_WKV + N4_WO + N4_BIA)

__device__ __forceinline__ void split4(const float* __restrict__ src,
                                       __nv_bfloat16* __restrict__ hi,
                                       __nv_bfloat16* __restrict__ lo, int i) {
    float4 v = ((const float4*)src)[i];
    float h0 = bf16_round(v.x), h1 = bf16_round(v.y);
    float h2 = bf16_round(v.z), h3 = bf16_round(v.w);
    uint32_t* hp = (uint32_t*)hi;
    uint32_t* lp = (uint32_t*)lo;
    hp[2 * i]     = pack_bf16x2(v.x, v.y);
    hp[2 * i + 1] = pack_bf16x2(v.z, v.w);
    lp[2 * i]     = pack_bf16x2(v.x - h0, v.y - h1);
    lp[2 * i + 1] = pack_bf16x2(v.z - h2, v.w - h3);
}

__global__ __launch_bounds__(256) void cvt_all(
    const float* __restrict__ x,  const float* __restrict__ Wq,
    const float* __restrict__ Wkv, const float* __restrict__ Wo,
    const float* __restrict__ bq,  const float* __restrict__ bkv,
    __nv_bfloat16* __restrict__ xh,  __nv_bfloat16* __restrict__ xl,
    __nv_bfloat16* __restrict__ wch, __nv_bfloat16* __restrict__ wcl,
    __nv_bfloat16* __restrict__ woh, __nv_bfloat16* __restrict__ wol,
    float* __restrict__ bqkv)
{
    int i = blockIdx.x * blockDim.x + threadIdx.x;
    if (i < N4_X) { split4(x, xh, xl, i); return; }
    i -= N4_X;
    if (i < N4_WQ) { split4(Wq, wch, wcl, i); return; }
    i -= N4_WQ;
    if (i < N4_WKV) { split4(Wkv, wch + (size_t)D * D, wcl + (size_t)D * D, i); return; }
    i -= N4_WKV;
    if (i < N4_WO) { split4(Wo, woh, wol, i); return; }
    i -= N4_WO;
    if (i < N4_BIA) {
        float4 v = (i < D / 4) ? ((const float4*)bq)[i]
                               : ((const float4*)bkv)[i - D / 4];
        ((float4*)bqkv)[i] = v;
    }
}

// ======================= mma.sync bf16x3 GEMM (16 warps) ==================
// CTA 128x128, 512 threads, warp grid 8(M)x2(N), warp tile 16x64.
// MODE 0: QKV epilogue = bias + smem-exchange RoPE + hi/lo split
// MODE 1: O epilogue   = bias + fp32 store
#define GK 2048
#define GBK 64
#define NCHUNK (GK / GBK)           // 32
#define TILE_BYTES 16384
#define STAGE_BYTES (4 * TILE_BYTES)
#define EPAD 132

template <int MODE>
__global__ __launch_bounds__(512, 1) void gemm_bf16x3(
    const __nv_bfloat16* __restrict__ Ah, const __nv_bfloat16* __restrict__ Al,
    const __nv_bfloat16* __restrict__ Wh, const __nv_bfloat16* __restrict__ Wl,
    const float* __restrict__ bias, float* __restrict__ C,
    const float* __restrict__ cosb, const float* __restrict__ sinb,
    __nv_bfloat16* __restrict__ qh, __nv_bfloat16* __restrict__ ql,
    __nv_bfloat16* __restrict__ kh, __nv_bfloat16* __restrict__ kl,
    __half* __restrict__ vh)
{
    extern __shared__ char smem_raw[];
    char* tiles = (char*)(((uintptr_t)smem_raw + 1023) & ~(uintptr_t)1023);
    const uint32_t tiles_u32 = smem_u32(tiles);

    const int tid  = threadIdx.x;
    const int wid  = tid >> 5;
    const int lane = tid & 31;
    const int bm = blockIdx.y * 128;
    const int bn = blockIdx.x * 128;
    const int wm = (wid & 7) * 16;
    const int wn = (wid >> 3) * 64;

    const __nv_bfloat16* srcs[4] = {Ah, Al, Wh, Wl};

    // 4096 16B chunks / 512 threads = 8 per thread
    auto load_chunk = [&](int k0, int s) {
        const uint32_t sb = tiles_u32 + s * STAGE_BYTES;
#pragma unroll
        for (int j = 0; j < 8; j++) {
            int e = tid + j * 512;
            int t = e >> 10;
            int r = (e >> 3) & 127;
            int c = (e & 7) * 8;
            int row = (t < 2 ? bm : bn) + r;
            const void* src = &srcs[t][(size_t)row * GK + k0 + c];
            uint32_t dst = sb + t * TILE_BYTES + SWZ128((uint32_t)(r * 128 + c * 2));
            cp_async16(dst, src);
        }
    };

    float c[8][4];
#pragma unroll
    for (int nt = 0; nt < 8; nt++)
#pragma unroll
        for (int q = 0; q < 4; q++) c[nt][q] = 0.f;

    const int mi = lane >> 3, rr = lane & 7;

    load_chunk(0, 0);          CP_COMMIT();
    load_chunk(GBK, 1);        CP_COMMIT();

    for (int i = 0; i < NCHUNK; i++) {
        CP_WAIT(1);
        __syncthreads();
        if (i + 2 < NCHUNK) load_chunk((i + 2) * GBK, (i + 2) % 3);
        CP_COMMIT();

        const uint32_t st   = tiles_u32 + (i % 3) * STAGE_BYTES;
        const uint32_t Ah_b = st;
        const uint32_t Al_b = st + TILE_BYTES;
        const uint32_t Wh_b = st + 2 * TILE_BYTES;
        const uint32_t Wl_b = st + 3 * TILE_BYTES;

#pragma unroll
        for (int k16 = 0; k16 < 4; k16++) {
            const int kb = k16 * 16;
            uint32_t ah[4], al[4];
            {
                const int m = wm + (mi & 1) * 8 + rr;
                const int k = kb + (mi >> 1) * 8;
                const uint32_t off = SWZ128((uint32_t)(m * 128 + k * 2));
                ldsm4(Ah_b + off, ah);
                ldsm4(Al_b + off, al);
            }
#pragma unroll
            for (int np = 0; np < 4; np++) {
                uint32_t bh4[4], bl4[4];
                const int n = wn + np * 16 + (mi >> 1) * 8 + rr;
                const int k = kb + (mi & 1) * 8;
                const uint32_t off = SWZ128((uint32_t)(n * 128 + k * 2));
                ldsm4(Wh_b + off, bh4);
                ldsm4(Wl_b + off, bl4);
#pragma unroll
                for (int half = 0; half < 2; half++) {
                    float* cc = c[np * 2 + half];
                    mma_bf16(cc, ah, bh4 + half * 2);
                    mma_bf16(cc, ah, bl4 + half * 2);
                    mma_bf16(cc, al, bh4 + half * 2);
                }
            }
        }
    }

    // ---- epilogue ----
    const int r0 = wm + (lane >> 2);       // row in CTA tile
    const int r1 = r0 + 8;
    const int cl2  = (lane & 3) * 2;
    const int tok0 = bm + r0;
    const int tok1 = bm + r1;

    // bias add
#pragma unroll
    for (int nt = 0; nt < 8; nt++) {
        const float b0 = bias[bn + wn + nt * 8 + cl2];
        const float b1 = bias[bn + wn + nt * 8 + cl2 + 1];
        c[nt][0] += b0; c[nt][1] += b1;
        c[nt][2] += b0; c[nt][3] += b1;
    }

    if (MODE == 1) {
#pragma unroll
        for (int nt = 0; nt < 8; nt++) {
            const int col = bn + wn + nt * 8 + cl2;
            *(float2*)&C[(size_t)tok0 * D + col] = make_float2(c[nt][0], c[nt][1]);
            *(float2*)&C[(size_t)tok1 * D + col] = make_float2(c[nt][2], c[nt][3]);
        }
        return;
    }

    // MODE 0: QKV epilogue. bn selects head: [0,D)=Q, [D,D+KDIM)=K, rest=V.
    if (bn >= D + KDIM) {
        // V head: direct fp16 store
        const int hbase = bn - D - KDIM;
#pragma unroll
        for (int nt = 0; nt < 8; nt++) {
            const int coln = wn + nt * 8 + cl2;
            *(uint32_t*)&vh[(size_t)tok0 * KDIM + hbase + coln] =
                pack_f16x2(c[nt][0], c[nt][1]);
            *(uint32_t*)&vh[(size_t)tok1 * KDIM + hbase + coln] =
                pack_f16x2(c[nt][2], c[nt][3]);
        }
        return;
    }

    // Q or K head: exchange through smem, then RoPE
    {
        float* ebuf = (float*)tiles;       // 128 x EPAD fp32 (re-use stages)
        __syncthreads();                   // mainloop smem no longer needed
#pragma unroll
        for (int nt = 0; nt < 8; nt++) {
            const int col = wn + nt * 8 + cl2;
            *(float2*)&ebuf[r0 * EPAD + col] = make_float2(c[nt][0], c[nt][1]);
            *(float2*)&ebuf[r1 * EPAD + col] = make_float2(c[nt][2], c[nt][3]);
        }
        __syncthreads();

        const bool isQ = (bn < D);
        const float sc = isQ ? SCALE : 1.0f;
        __nv_bfloat16* dh = isQ ? qh : kh;
        __nv_bfloat16* dl = isQ ? ql : kl;
        const int hbase  = isQ ? bn : (bn - D);
        const int rowstr = isQ ? D : KDIM;
        const int ngrp   = wid >> 3;       // 0/1: d-range 0..31 / 32..63

#pragma unroll
        for (int nt = 0; nt < 4; nt++) {
            const int d = ngrp * 32 + nt * 8 + cl2;
#pragma unroll
            for (int rsel = 0; rsel < 2; rsel++) {
                const int rloc = rsel ? r1 : r0;
                const int tok  = bm + rloc;
                const float ax = ebuf[rloc * EPAD + d];
                const float ay = ebuf[rloc * EPAD + d + 1];
                const float bx = ebuf[rloc * EPAD + d + 64];
                const float by = ebuf[rloc * EPAD + d + 65];
                const float2 ca = *(const float2*)&cosb[(size_t)tok * HD + d];
                const float2 sa = *(const float2*)&sinb[(size_t)tok * HD + d];
                const float2 cb = *(const float2*)&cosb[(size_t)tok * HD + d + 64];
                const float2 sb2 = *(const float2*)&sinb[(size_t)tok * HD + d + 64];
                const float e0x = (ax * ca.x - bx * sa.x) * sc;
                const float e0y = (ay * ca.y - by * sa.y) * sc;
                const float e1x = (bx * cb.x + ax * sb2.x) * sc;
                const float e1y = (by * cb.y + ay * sb2.y) * sc;
                const size_t o = (size_t)tok * rowstr + hbase + d;
                float h0, h1;
                h0 = bf16_round(e0x); h1 = bf16_round(e0y);
                *(uint32_t*)&dh[o]      = pack_bf16x2(e0x, e0y);
                *(uint32_t*)&dl[o]      = pack_bf16x2(e0x - h0, e0y - h1);
                h0 = bf16_round(e1x); h1 = bf16_round(e1y);
                *(uint32_t*)&dh[o + 64] = pack_bf16x2(e1x, e1y);
                *(uint32_t*)&dl[o + 64] = pack_bf16x2(e1x - h0, e1y - h1);
            }
        }
    }
}

// ======================= flash attention (bf16x3 QK, fp16 PV) =============
#define FBM 128
#define FBN 64
#define KP  136
#define KT_BYTES (FBN * KP * 2)       // 17408
#define FSTG (3 * KT_BYTES)

__global__ __launch_bounds__(256, 1) void flash_mma(
    const __nv_bfloat16* __restrict__ Qh, const __nv_bfloat16* __restrict__ Ql,
    const __nv_bfloat16* __restrict__ Kh, const __nv_bfloat16* __restrict__ Kl,
    const __half* __restrict__ Vh,
    __nv_bfloat16* __restrict__ Ah, __nv_bfloat16* __restrict__ Al)
{
    extern __shared__ char smem_raw[];
    const uint32_t smem = smem_u32(smem_raw);

    const int tid  = threadIdx.x;
    const int w    = tid >> 5;
    const int lane = tid & 31;
    const int qblk = gridDim.x - 1 - blockIdx.x;   // longest-first
    const int m0   = qblk * FBM;
    const int bh   = blockIdx.y;
    const int b    = bh / H;
    const int h    = bh % H;
    const int kvh  = h / GROUPS;

    const int rowg0 = m0 + w * 16 + (lane >> 2);
    const int rowg1 = rowg0 + 8;

    uint32_t qh[8][4], ql[8][4];
    {
        const size_t base0 = ((size_t)(b * L + rowg0) * H + h) * HD;
        const size_t base1 = base0 + (size_t)8 * H * HD;
#pragma unroll
        for (int j = 0; j < 8; j++) {
            const int c0 = j * 16 + (lane & 3) * 2;
            qh[j][0] = *(const uint32_t*)&Qh[base0 + c0];
            qh[j][1] = *(const uint32_t*)&Qh[base1 + c0];
            qh[j][2] = *(const uint32_t*)&Qh[base0 + c0 + 8];
            qh[j][3] = *(const uint32_t*)&Qh[base1 + c0 + 8];
            ql[j][0] = *(const uint32_t*)&Ql[base0 + c0];
            ql[j][1] = *(const uint32_t*)&Ql[base1 + c0];
            ql[j][2] = *(const uint32_t*)&Ql[base0 + c0 + 8];
            ql[j][3] = *(const uint32_t*)&Ql[base1 + c0 + 8];
        }
    }

    const void* kvsrc[3] = {Kh, Kl, Vh};
    auto load_kv = [&](int t, int s) {
        const int n0 = t * FBN;
        const uint32_t sb = smem + s * FSTG;
#pragma unroll
        for (int jj = 0; jj < 12; jj++) {
            int e = tid + jj * 256;
            int buf = e >> 10;
            int r   = (e >> 4) & 63;
            int ch  = e & 15;
            const size_t el = ((size_t)(b * L + n0 + r) * HKV + kvh) * HD + ch * 8;
            const void* src = (const char*)kvsrc[buf] + el * 2;
            uint32_t dst = sb + buf * KT_BYTES + (uint32_t)(r * KP + ch * 8) * 2;
            cp_async16(dst, src);
        }
    };

    float o[16][4];
#pragma unroll
    for (int nt = 0; nt < 16; nt++)
#pragma unroll
        for (int q = 0; q < 4; q++) o[nt][q] = 0.f;
    float mrow0 = -1e30f, mrow1 = -1e30f, lrow0 = 0.f, lrow1 = 0.f;

    const int ntiles = m0 / FBN + 2;
    load_kv(0, 0);
    CP_COMMIT();

    const int rlane = lane & 7;
    const int khalf = (lane >> 3) & 1;
    const int npair = lane >> 4;

    for (int t = 0; t < ntiles; t++) {
        CP_WAIT(0);
        __syncthreads();
        if (t + 1 < ntiles) load_kv(t + 1, (t + 1) & 1);
        CP_COMMIT();

        const int n0 = t * FBN;
        if (n0 > m0 + w * 16 + 15) continue;

        const uint32_t st  = smem + (t & 1) * FSTG;
        const uint32_t Khs = st;
        const uint32_t Kls = st + KT_BYTES;
        const uint32_t Vhs = st + 2 * KT_BYTES;

        float s8[8][4];
#pragma unroll
        for (int nt = 0; nt < 8; nt++)
#pragma unroll
            for (int q = 0; q < 4; q++) s8[nt][q] = 0.f;

#pragma unroll
        for (int j = 0; j < 8; j++) {
#pragma unroll
            for (int nt = 0; nt < 8; nt += 2) {
                uint32_t kb4[4], kl4[4];
                const uint32_t a = (uint32_t)(((nt + npair) * 8 + rlane) * KP
                                              + j * 16 + khalf * 8) * 2;
                ldsm4(Khs + a, kb4);
                ldsm4(Kls + a, kl4);
                mma_bf16(s8[nt],     qh[j], kb4);
                mma_bf16(s8[nt],     qh[j], kl4);
                mma_bf16(s8[nt],     ql[j], kb4);
                mma_bf16(s8[nt + 1], qh[j], kb4 + 2);
                mma_bf16(s8[nt + 1], qh[j], kl4 + 2);
                mma_bf16(s8[nt + 1], ql[j], kb4 + 2);
            }
        }

        if (t >= ntiles - 2) {
            const int colc = n0 + (lane & 3) * 2;
#pragma unroll
            for (int nt = 0; nt < 8; nt++) {
                const int cg = colc + nt * 8;
                if (cg     > rowg0) s8[nt][0] = -1e30f;
                if (cg + 1 > rowg0) s8[nt][1] = -1e30f;
                if (cg     > rowg1) s8[nt][2] = -1e30f;
                if (cg + 1 > rowg1) s8[nt][3] = -1e30f;
            }
        }

        float mx0 = -1e30f, mx1 = -1e30f;
#pragma unroll
        for (int nt = 0; nt < 8; nt++) {
            mx0 = fmaxf(mx0, fmaxf(s8[nt][0], s8[nt][1]));
            mx1 = fmaxf(mx1, fmaxf(s8[nt][2], s8[nt][3]));
        }
        mx0 = fmaxf(mx0, __shfl_xor_sync(0xffffffffu, mx0, 1));
        mx0 = fmaxf(mx0, __shfl_xor_sync(0xffffffffu, mx0, 2));
        mx1 = fmaxf(mx1, __shfl_xor_sync(0xffffffffu, mx1, 1));
        mx1 = fmaxf(mx1, __shfl_xor_sync(0xffffffffu, mx1, 2));

        const float mn0 = fmaxf(mrow0, mx0);
        const float mn1 = fmaxf(mrow1, mx1);
        const float alpha0 = __expf(mrow0 - mn0);
        const float alpha1 = __expf(mrow1 - mn1);

        float sum0 = 0.f, sum1 = 0.f;
#pragma unroll
        for (int nt = 0; nt < 8; nt++) {
            s8[nt][0] = __expf(s8[nt][0] - mn0);
            s8[nt][1] = __expf(s8[nt][1] - mn0);
            s8[nt][2] = __expf(s8[nt][2] - mn1);
            s8[nt][3] = __expf(s8[nt][3] - mn1);
            sum0 += s8[nt][0] + s8[nt][1];
            sum1 += s8[nt][2] + s8[nt][3];
        }
        sum0 += __shfl_xor_sync(0xffffffffu, sum0, 1);
        sum0 += __shfl_xor_sync(0xffffffffu, sum0, 2);
        sum1 += __shfl_xor_sync(0xffffffffu, sum1, 1);
        sum1 += __shfl_xor_sync(0xffffffffu, sum1, 2);

        lrow0 = lrow0 * alpha0 + sum0;
        lrow1 = lrow1 * alpha1 + sum1;
        mrow0 = mn0; mrow1 = mn1;

#pragma unroll
        for (int nt = 0; nt < 16; nt++) {
            o[nt][0] *= alpha0; o[nt][1] *= alpha0;
            o[nt][2] *= alpha1; o[nt][3] *= alpha1;
        }

#pragma unroll
        for (int kt = 0; kt < 4; kt++) {
            uint32_t ph4[4];
            {
                const float* p0 = s8[2 * kt];
                const float* p1 = s8[2 * kt + 1];
                ph4[0] = pack_f16x2(p0[0], p0[1]);
                ph4[1] = pack_f16x2(p0[2], p0[3]);
                ph4[2] = pack_f16x2(p1[0], p1[1]);
                ph4[3] = pack_f16x2(p1[2], p1[3]);
            }
#pragma unroll
            for (int nt = 0; nt < 16; nt += 2) {
                uint32_t vh4[4];
                const uint32_t a = (uint32_t)((kt * 16 + khalf * 8 + rlane) * KP
                                              + (nt + npair) * 8) * 2;
                ldsm4t(Vhs + a, vh4);
                mma_f16(o[nt],     ph4, vh4);
                mma_f16(o[nt + 1], ph4, vh4 + 2);
            }
        }
    }

    const float inv0 = 1.f / lrow0;
    const float inv1 = 1.f / lrow1;
    const size_t base0 = ((size_t)(b * L + rowg0) * H + h) * HD;
    const size_t base1 = base0 + (size_t)8 * H * HD;
#pragma unroll
    for (int nt = 0; nt < 16; nt++) {
        const int col = nt * 8 + (lane & 3) * 2;
        const float f0 = o[nt][0] * inv0, f1 = o[nt][1] * inv0;
        const float f2 = o[nt][2] * inv1, f3 = o[nt][3] * inv1;
        const float h0 = bf16_round(f0), h1 = bf16_round(f1);
        const float h2 = bf16_round(f2), h3 = bf16_round(f3);
        *(uint32_t*)&Ah[base0 + col] = pack_bf16x2(f0, f1);
        *(uint32_t*)&Ah[base1 + col] = pack_bf16x2(f2, f3);
        *(uint32_t*)&Al[base0 + col] = pack_bf16x2(f0 - h0, f1 - h1);
        *(uint32_t*)&Al[base1 + col] = pack_bf16x2(f2 - h2, f3 - h3);
    }
}

// ===========================================================================
extern "C" void kernel_launch(void* const* d_in, const int* in_sizes, int n_in,
                              void* d_out, int out_size)
{
    (void)in_sizes; (void)n_in; (void)out_size;
    const float* x    = (const float*)d_in[0];
    const float* cosb = (const float*)d_in[1];
    const float* sinb = (const float*)d_in[2];
    const float* Wq   = (const float*)d_in[3];
    const float* bq   = (const float*)d_in[4];
    const float* Wkv  = (const float*)d_in[5];
    const float* bkv  = (const float*)d_in[6];
    const float* Wo   = (const float*)d_in[7];
    const float* bo   = (const float*)d_in[8];
    float* out = (float*)d_out;

    float *bqkv;
    __nv_bfloat16 *xh, *xl, *wch, *wcl, *woh, *wol;
    __nv_bfloat16 *qh, *ql, *kh, *kl, *ah, *al;
    __half *vh;
    cudaGetSymbolAddress((void**)&bqkv, g_bqkv);
    cudaGetSymbolAddress((void**)&xh,  g_xh);
    cudaGetSymbolAddress((void**)&xl,  g_xl);
    cudaGetSymbolAddress((void**)&wch, g_wch);
    cudaGetSymbolAddress((void**)&wcl, g_wcl);
    cudaGetSymbolAddress((void**)&woh, g_woh);
    cudaGetSymbolAddress((void**)&wol, g_wol);
    cudaGetSymbolAddress((void**)&qh,  g_qh);
    cudaGetSymbolAddress((void**)&ql,  g_ql);
    cudaGetSymbolAddress((void**)&kh,  g_kh);
    cudaGetSymbolAddress((void**)&kl,  g_kl);
    cudaGetSymbolAddress((void**)&vh,  g_vh);
    cudaGetSymbolAddress((void**)&ah,  g_ah);
    cudaGetSymbolAddress((void**)&al,  g_al);

    const int gemm_smem = 1024 + 3 * STAGE_BYTES;
    cudaFuncSetAttribute(gemm_bf16x3<0>, cudaFuncAttributeMaxDynamicSharedMemorySize,
                         gemm_smem);
    cudaFuncSetAttribute(gemm_bf16x3<1>, cudaFuncAttributeMaxDynamicSharedMemorySize,
                         gemm_smem);
    const int fa_smem = 2 * FSTG;
    cudaFuncSetAttribute(flash_mma, cudaFuncAttributeMaxDynamicSharedMemorySize,
                         fa_smem);

    // fused conversion: x + concat(Wq,Wkv) + Wo + concat bias
    cvt_all<<<(N4_TOT + 255) / 256, 256>>>(x, Wq, Wkv, Wo, bq, bkv,
                                           xh, xl, wch, wcl, woh, wol, bqkv);

    // fused QKV projection with RoPE+split epilogue
    gemm_bf16x3<0><<<dim3(QKVD / 128, M_TOK / 128), 512, gemm_smem>>>(
        xh, xl, wch, wcl, bqkv, nullptr, cosb, sinb, qh, ql, kh, kl, vh);

    // tensor-core flash attention -> Ah/Al splits
    flash_mma<<<dim3(L / FBM, B * H), 256, fa_smem>>>(
        qh, ql, kh, kl, vh, ah, al);

    // O projection
    gemm_bf16x3<1><<<dim3(D / 128, M_TOK / 128), 512, gemm_smem>>>(
        ah, al, woh, wol, bo, out, nullptr, nullptr,
        nullptr, nullptr, nullptr, nullptr, nullptr);
}

// round 16
// speedup vs baseline: 1.1754x; 1.0616x over previous
#include <cuda_runtime.h>
#include <cuda_bf16.h>
#include <cuda_fp16.h>
#include <math.h>
#include <stdint.h>

#define B 2
#define L 2048
#define D 2048
#define H 16
#define HKV 4
#define HD 128
#define GROUPS (H / HKV)
#define M_TOK (B * L)          // 4096 tokens
#define KVDIM (2 * HKV * HD)   // 1024
#define KDIM  (HKV * HD)       // 512
#define QKVD (D + KVDIM)       // 3072
#define SCALE 0.08838834764831845f

// ---------------- scratch ---------------------------------------------------
__device__ float g_bqkv[QKVD];
__device__ __nv_bfloat16 g_xh[(size_t)M_TOK * D];
__device__ __nv_bfloat16 g_xl[(size_t)M_TOK * D];
__device__ __nv_bfloat16 g_wch[(size_t)QKVD * D];
__device__ __nv_bfloat16 g_wcl[(size_t)QKVD * D];
__device__ __nv_bfloat16 g_woh[(size_t)D * D];
__device__ __nv_bfloat16 g_wol[(size_t)D * D];
__device__ __nv_bfloat16 g_qh[(size_t)M_TOK * D];
__device__ __nv_bfloat16 g_ql[(size_t)M_TOK * D];
__device__ __nv_bfloat16 g_kh[(size_t)M_TOK * KDIM];
__device__ __nv_bfloat16 g_kl[(size_t)M_TOK * KDIM];
__device__ __half g_vh[(size_t)M_TOK * KDIM];
__device__ __nv_bfloat16 g_ah[(size_t)M_TOK * D];
__device__ __nv_bfloat16 g_al[(size_t)M_TOK * D];

// ======================= helpers ==========================================
__device__ __forceinline__ uint32_t smem_u32(const void* p) {
    uint32_t a;
    asm("{ .reg .u64 t; cvta.to.shared.u64 t, %1; cvt.u32.u64 %0, t; }"
        : "=r"(a) : "l"(p));
    return a;
}
#define SWZ128(off) ((off) ^ (((off) >> 3) & 0x70))

__device__ __forceinline__ void ldsm4(uint32_t addr, uint32_t* r) {
    asm volatile("ldmatrix.sync.aligned.m8n8.x4.shared.b16 {%0,%1,%2,%3}, [%4];"
                 : "=r"(r[0]), "=r"(r[1]), "=r"(r[2]), "=r"(r[3]) : "r"(addr));
}
__device__ __forceinline__ void ldsm4t(uint32_t addr, uint32_t* r) {
    asm volatile("ldmatrix.sync.aligned.m8n8.x4.trans.shared.b16 {%0,%1,%2,%3}, [%4];"
                 : "=r"(r[0]), "=r"(r[1]), "=r"(r[2]), "=r"(r[3]) : "r"(addr));
}
__device__ __forceinline__ void mma_bf16(float* c, const uint32_t* a,
                                         const uint32_t* b) {
    asm volatile(
        "mma.sync.aligned.m16n8k16.row.col.f32.bf16.bf16.f32 "
        "{%0,%1,%2,%3}, {%4,%5,%6,%7}, {%8,%9}, {%0,%1,%2,%3};"
        : "+f"(c[0]), "+f"(c[1]), "+f"(c[2]), "+f"(c[3])
        : "r"(a[0]), "r"(a[1]), "r"(a[2]), "r"(a[3]), "r"(b[0]), "r"(b[1]));
}
__device__ __forceinline__ void mma_f16(float* c, const uint32_t* a,
                                        const uint32_t* b) {
    asm volatile(
        "mma.sync.aligned.m16n8k16.row.col.f32.f16.f16.f32 "
        "{%0,%1,%2,%3}, {%4,%5,%6,%7}, {%8,%9}, {%0,%1,%2,%3};"
        : "+f"(c[0]), "+f"(c[1]), "+f"(c[2]), "+f"(c[3])
        : "r"(a[0]), "r"(a[1]), "r"(a[2]), "r"(a[3]), "r"(b[0]), "r"(b[1]));
}
__device__ __forceinline__ void cp_async16(uint32_t dst, const void* src) {
    asm volatile("cp.async.cg.shared.global [%0], [%1], 16;"
                 :: "r"(dst), "l"(src));
}
#define CP_COMMIT() asm volatile("cp.async.commit_group;" ::: "memory")
#define CP_WAIT(N)  asm volatile("cp.async.wait_group %0;" :: "n"(N) : "memory")

__device__ __forceinline__ uint32_t pack_bf16x2(float lo, float hi) {
    uint32_t r;
    asm("cvt.rn.bf16x2.f32 %0, %1, %2;" : "=r"(r) : "f"(hi), "f"(lo));
    return r;
}
__device__ __forceinline__ uint32_t pack_f16x2(float lo, float hi) {
    uint32_t r;
    asm("cvt.rn.f16x2.f32 %0, %1, %2;" : "=r"(r) : "f"(hi), "f"(lo));
    return r;
}
__device__ __forceinline__ float bf16_round(float x) {
    return __bfloat162float(__float2bfloat16(x));
}

// ======================= fused hi/lo split (x + weights + bias) ===========
#define N4_X   ((M_TOK * D) / 4)
#define N4_WQ  ((D * D) / 4)
#define N4_WKV ((KVDIM * D) / 4)
#define N4_WO  ((D * D) / 4)
#define N4_BIA (QKVD / 4)
#define N4_TOT (N4_X + N4_WQ + N4_WKV + N4_WO + N4_BIA)

__device__ __forceinline__ void split4(const float* __restrict__ src,
                                       __nv_bfloat16* __restrict__ hi,
                                       __nv_bfloat16* __restrict__ lo, int i) {
    float4 v = ((const float4*)src)[i];
    float h0 = bf16_round(v.x), h1 = bf16_round(v.y);
    float h2 = bf16_round(v.z), h3 = bf16_round(v.w);
    uint32_t* hp = (uint32_t*)hi;
    uint32_t* lp = (uint32_t*)lo;
    hp[2 * i]     = pack_bf16x2(v.x, v.y);
    hp[2 * i + 1] = pack_bf16x2(v.z, v.w);
    lp[2 * i]     = pack_bf16x2(v.x - h0, v.y - h1);
    lp[2 * i + 1] = pack_bf16x2(v.z - h2, v.w - h3);
}

__global__ __launch_bounds__(256) void cvt_all(
    const float* __restrict__ x,  const float* __restrict__ Wq,
    const float* __restrict__ Wkv, const float* __restrict__ Wo,
    const float* __restrict__ bq,  const float* __restrict__ bkv,
    __nv_bfloat16* __restrict__ xh,  __nv_bfloat16* __restrict__ xl,
    __nv_bfloat16* __restrict__ wch, __nv_bfloat16* __restrict__ wcl,
    __nv_bfloat16* __restrict__ woh, __nv_bfloat16* __restrict__ wol,
    float* __restrict__ bqkv)
{
    int i = blockIdx.x * blockDim.x + threadIdx.x;
    if (i < N4_X) { split4(x, xh, xl, i); return; }
    i -= N4_X;
    if (i < N4_WQ) { split4(Wq, wch, wcl, i); return; }
    i -= N4_WQ;
    if (i < N4_WKV) { split4(Wkv, wch + (size_t)D * D, wcl + (size_t)D * D, i); return; }
    i -= N4_WKV;
    if (i < N4_WO) { split4(Wo, woh, wol, i); return; }
    i -= N4_WO;
    if (i < N4_BIA) {
        float4 v = (i < D / 4) ? ((const float4*)bq)[i]
                               : ((const float4*)bkv)[i - D / 4];
        ((float4*)bqkv)[i] = v;
    }
}

// ======================= mma.sync bf16x3 GEMM =============================
// CTA 256(M)x128(N), 512 threads, warp grid 8(M)x2(N), warp tile 32x64.
// 2-stage cp.async double buffer (96 KB/stage).
// MODE 0: QKV epilogue = bias + smem-exchange RoPE + hi/lo split
// MODE 1: O epilogue   = bias + fp32 store
#define GK 2048
#define GBK 64
#define NCHUNK (GK / GBK)           // 32
#define A_TILE_B 32768              // 256 rows * 128B
#define B_TILE_B 16384              // 128 rows * 128B
#define STAGE_B2 (2 * A_TILE_B + 2 * B_TILE_B)   // 98304
#define EPAD 132

template <int MODE>
__global__ __launch_bounds__(512, 1) void gemm_bf16x3(
    const __nv_bfloat16* __restrict__ Ah, const __nv_bfloat16* __restrict__ Al,
    const __nv_bfloat16* __restrict__ Wh, const __nv_bfloat16* __restrict__ Wl,
    const float* __restrict__ bias, float* __restrict__ C,
    const float* __restrict__ cosb, const float* __restrict__ sinb,
    __nv_bfloat16* __restrict__ qh, __nv_bfloat16* __restrict__ ql,
    __nv_bfloat16* __restrict__ kh, __nv_bfloat16* __restrict__ kl,
    __half* __restrict__ vh)
{
    extern __shared__ char smem_raw[];
    char* tiles = (char*)(((uintptr_t)smem_raw + 1023) & ~(uintptr_t)1023);
    const uint32_t tiles_u32 = smem_u32(tiles);

    const int tid  = threadIdx.x;
    const int wid  = tid >> 5;
    const int lane = tid & 31;
    const int bm = blockIdx.y * 256;
    const int bn = blockIdx.x * 128;
    const int wm = (wid & 7) * 32;
    const int wn = (wid >> 3) * 64;

    const __nv_bfloat16* asrc[2] = {Ah, Al};
    const __nv_bfloat16* wsrc[2] = {Wh, Wl};

    // 6144 16B-chunks per stage / 512 threads = 12 per thread
    auto load_chunk = [&](int k0, int s) {
        const uint32_t sb = tiles_u32 + s * STAGE_B2;
#pragma unroll
        for (int j = 0; j < 12; j++) {
            int e = tid + j * 512;
            if (e < 4096) {                 // A tiles (256 rows x 8 chunks) x2
                int t = e >> 11;
                int idx = e & 2047;
                int r = idx >> 3;
                int c8 = (idx & 7) * 8;
                const void* src = &asrc[t][(size_t)(bm + r) * GK + k0 + c8];
                uint32_t dst = sb + t * A_TILE_B + SWZ128((uint32_t)(r * 128 + c8 * 2));
                cp_async16(dst, src);
            } else {                        // B tiles (128 rows x 8 chunks) x2
                int e2 = e - 4096;
                int t = e2 >> 10;
                int idx = e2 & 1023;
                int r = idx >> 3;
                int c8 = (idx & 7) * 8;
                const void* src = &wsrc[t][(size_t)(bn + r) * GK + k0 + c8];
                uint32_t dst = sb + 2 * A_TILE_B + t * B_TILE_B
                             + SWZ128((uint32_t)(r * 128 + c8 * 2));
                cp_async16(dst, src);
            }
        }
    };

    float c[2][8][4];
#pragma unroll
    for (int mt = 0; mt < 2; mt++)
#pragma unroll
        for (int nt = 0; nt < 8; nt++)
#pragma unroll
            for (int q = 0; q < 4; q++) c[mt][nt][q] = 0.f;

    const int mi = lane >> 3, rr = lane & 7;

    load_chunk(0, 0);
    CP_COMMIT();

    for (int i = 0; i < NCHUNK; i++) {
        if (i + 1 < NCHUNK) {
            load_chunk((i + 1) * GBK, (i + 1) & 1);
            CP_COMMIT();
            CP_WAIT(1);
        } else {
            CP_WAIT(0);
        }
        __syncthreads();

        const uint32_t st   = tiles_u32 + (i & 1) * STAGE_B2;
        const uint32_t Ah_b = st;
        const uint32_t Al_b = st + A_TILE_B;
        const uint32_t Wh_b = st + 2 * A_TILE_B;
        const uint32_t Wl_b = st + 2 * A_TILE_B + B_TILE_B;

#pragma unroll
        for (int k16 = 0; k16 < 4; k16++) {
            const int kb = k16 * 16;
            uint32_t ah[2][4], al[2][4];
#pragma unroll
            for (int mt = 0; mt < 2; mt++) {
                const int m = wm + mt * 16 + (mi & 1) * 8 + rr;
                const int k = kb + (mi >> 1) * 8;
                const uint32_t off = SWZ128((uint32_t)(m * 128 + k * 2));
                ldsm4(Ah_b + off, ah[mt]);
                ldsm4(Al_b + off, al[mt]);
            }
#pragma unroll
            for (int np = 0; np < 4; np++) {
                uint32_t bh4[4], bl4[4];
                const int n = wn + np * 16 + (mi >> 1) * 8 + rr;
                const int k = kb + (mi & 1) * 8;
                const uint32_t off = SWZ128((uint32_t)(n * 128 + k * 2));
                ldsm4(Wh_b + off, bh4);
                ldsm4(Wl_b + off, bl4);
#pragma unroll
                for (int mt = 0; mt < 2; mt++)
#pragma unroll
                    for (int half = 0; half < 2; half++) {
                        float* cc = c[mt][np * 2 + half];
                        mma_bf16(cc, ah[mt], bh4 + half * 2);
                        mma_bf16(cc, ah[mt], bl4 + half * 2);
                        mma_bf16(cc, al[mt], bh4 + half * 2);
                    }
            }
        }
        __syncthreads();
    }

    // ---- epilogue ----
    const int cl2 = (lane & 3) * 2;

    // bias add
#pragma unroll
    for (int nt = 0; nt < 8; nt++) {
        const float b0 = bias[bn + wn + nt * 8 + cl2];
        const float b1 = bias[bn + wn + nt * 8 + cl2 + 1];
#pragma unroll
        for (int mt = 0; mt < 2; mt++) {
            c[mt][nt][0] += b0; c[mt][nt][1] += b1;
            c[mt][nt][2] += b0; c[mt][nt][3] += b1;
        }
    }

    if (MODE == 1) {
#pragma unroll
        for (int mt = 0; mt < 2; mt++) {
            const int row0 = bm + wm + mt * 16 + (lane >> 2);
#pragma unroll
            for (int nt = 0; nt < 8; nt++) {
                const int col = bn + wn + nt * 8 + cl2;
                *(float2*)&C[(size_t)row0 * D + col] =
                    make_float2(c[mt][nt][0], c[mt][nt][1]);
                *(float2*)&C[(size_t)(row0 + 8) * D + col] =
                    make_float2(c[mt][nt][2], c[mt][nt][3]);
            }
        }
        return;
    }

    // MODE 0: QKV epilogue. bn selects: [0,D)=Q, [D,D+KDIM)=K, rest=V.
    if (bn >= D + KDIM) {
        const int hbase = bn - D - KDIM;
#pragma unroll
        for (int mt = 0; mt < 2; mt++) {
            const int row0 = bm + wm + mt * 16 + (lane >> 2);
#pragma unroll
            for (int nt = 0; nt < 8; nt++) {
                const int coln = wn + nt * 8 + cl2;
                *(uint32_t*)&vh[(size_t)row0 * KDIM + hbase + coln] =
                    pack_f16x2(c[mt][nt][0], c[mt][nt][1]);
                *(uint32_t*)&vh[(size_t)(row0 + 8) * KDIM + hbase + coln] =
                    pack_f16x2(c[mt][nt][2], c[mt][nt][3]);
            }
        }
        return;
    }

    // Q or K head: exchange through smem, then RoPE
    {
        float* ebuf = (float*)tiles;       // 256 x EPAD fp32 (135 KB, fits)
#pragma unroll
        for (int mt = 0; mt < 2; mt++) {
            const int r0 = wm + mt * 16 + (lane >> 2);
#pragma unroll
            for (int nt = 0; nt < 8; nt++) {
                const int col = wn + nt * 8 + cl2;
                *(float2*)&ebuf[r0 * EPAD + col] =
                    make_float2(c[mt][nt][0], c[mt][nt][1]);
                *(float2*)&ebuf[(r0 + 8) * EPAD + col] =
                    make_float2(c[mt][nt][2], c[mt][nt][3]);
            }
        }
        __syncthreads();

        const bool isQ = (bn < D);
        const float sc = isQ ? SCALE : 1.0f;
        __nv_bfloat16* dh = isQ ? qh : kh;
        __nv_bfloat16* dl = isQ ? ql : kl;
        const int hbase  = isQ ? bn : (bn - D);
        const int rowstr = isQ ? D : KDIM;
        const int ngrp   = wid >> 3;       // 0/1: d-range 0..31 / 32..63

#pragma unroll
        for (int mt = 0; mt < 2; mt++) {
#pragma unroll
            for (int rsel = 0; rsel < 2; rsel++) {
                const int rloc = wm + mt * 16 + (lane >> 2) + rsel * 8;
                const int tok  = bm + rloc;
#pragma unroll
                for (int nt = 0; nt < 4; nt++) {
                    const int d = ngrp * 32 + nt * 8 + cl2;
                    const float ax = ebuf[rloc * EPAD + d];
                    const float ay = ebuf[rloc * EPAD + d + 1];
                    const float bx = ebuf[rloc * EPAD + d + 64];
                    const float by = ebuf[rloc * EPAD + d + 65];
                    const float2 ca = *(const float2*)&cosb[(size_t)tok * HD + d];
                    const float2 sa = *(const float2*)&sinb[(size_t)tok * HD + d];
                    const float2 cb = *(const float2*)&cosb[(size_t)tok * HD + d + 64];
                    const float2 sb2 = *(const float2*)&sinb[(size_t)tok * HD + d + 64];
                    const float e0x = (ax * ca.x - bx * sa.x) * sc;
                    const float e0y = (ay * ca.y - by * sa.y) * sc;
                    const float e1x = (bx * cb.x + ax * sb2.x) * sc;
                    const float e1y = (by * cb.y + ay * sb2.y) * sc;
                    const size_t o = (size_t)tok * rowstr + hbase + d;
                    float h0, h1;
                    h0 = bf16_round(e0x); h1 = bf16_round(e0y);
                    *(uint32_t*)&dh[o]      = pack_bf16x2(e0x, e0y);
                    *(uint32_t*)&dl[o]      = pack_bf16x2(e0x - h0, e0y - h1);
                    h0 = bf16_round(e1x); h1 = bf16_round(e1y);
                    *(uint32_t*)&dh[o + 64] = pack_bf16x2(e1x, e1y);
                    *(uint32_t*)&dl[o + 64] = pack_bf16x2(e1x - h0, e1y - h1);
                }
            }
        }
    }
}

// ======================= flash attention (bf16x3 QK, fp16 PV) =============
#define FBM 128
#define FBN 64
#define KP  136
#define KT_BYTES (FBN * KP * 2)       // 17408
#define FSTG (3 * KT_BYTES)

__global__ __launch_bounds__(256, 1) void flash_mma(
    const __nv_bfloat16* __restrict__ Qh, const __nv_bfloat16* __restrict__ Ql,
    const __nv_bfloat16* __restrict__ Kh, const __nv_bfloat16* __restrict__ Kl,
    const __half* __restrict__ Vh,
    __nv_bfloat16* __restrict__ Ah, __nv_bfloat16* __restrict__ Al)
{
    extern __shared__ char smem_raw[];
    const uint32_t smem = smem_u32(smem_raw);

    const int tid  = threadIdx.x;
    const int w    = tid >> 5;
    const int lane = tid & 31;
    const int qblk = gridDim.x - 1 - blockIdx.x;   // longest-first
    const int m0   = qblk * FBM;
    const int bh   = blockIdx.y;
    const int b    = bh / H;
    const int h    = bh % H;
    const int kvh  = h / GROUPS;

    const int rowg0 = m0 + w * 16 + (lane >> 2);
    const int rowg1 = rowg0 + 8;

    uint32_t qh[8][4], ql[8][4];
    {
        const size_t base0 = ((size_t)(b * L + rowg0) * H + h) * HD;
        const size_t base1 = base0 + (size_t)8 * H * HD;
#pragma unroll
        for (int j = 0; j < 8; j++) {
            const int c0 = j * 16 + (lane & 3) * 2;
            qh[j][0] = *(const uint32_t*)&Qh[base0 + c0];
            qh[j][1] = *(const uint32_t*)&Qh[base1 + c0];
            qh[j][2] = *(const uint32_t*)&Qh[base0 + c0 + 8];
            qh[j][3] = *(const uint32_t*)&Qh[base1 + c0 + 8];
            ql[j][0] = *(const uint32_t*)&Ql[base0 + c0];
            ql[j][1] = *(const uint32_t*)&Ql[base1 + c0];
            ql[j][2] = *(const uint32_t*)&Ql[base0 + c0 + 8];
            ql[j][3] = *(const uint32_t*)&Ql[base1 + c0 + 8];
        }
    }

    const void* kvsrc[3] = {Kh, Kl, Vh};
    auto load_kv = [&](int t, int s) {
        const int n0 = t * FBN;
        const uint32_t sb = smem + s * FSTG;
#pragma unroll
        for (int jj = 0; jj < 12; jj++) {
            int e = tid + jj * 256;
            int buf = e >> 10;
            int r   = (e >> 4) & 63;
            int ch  = e & 15;
            const size_t el = ((size_t)(b * L + n0 + r) * HKV + kvh) * HD + ch * 8;
            const void* src = (const char*)kvsrc[buf] + el * 2;
            uint32_t dst = sb + buf * KT_BYTES + (uint32_t)(r * KP + ch * 8) * 2;
            cp_async16(dst, src);
        }
    };

    float o[16][4];
#pragma unroll
    for (int nt = 0; nt < 16; nt++)
#pragma unroll
        for (int q = 0; q < 4; q++) o[nt][q] = 0.f;
    float mrow0 = -1e30f, mrow1 = -1e30f, lrow0 = 0.f, lrow1 = 0.f;

    const int ntiles = m0 / FBN + 2;
    load_kv(0, 0);
    CP_COMMIT();

    const int rlane = lane & 7;
    const int khalf = (lane >> 3) & 1;
    const int npair = lane >> 4;

    for (int t = 0; t < ntiles; t++) {
        CP_WAIT(0);
        __syncthreads();
        if (t + 1 < ntiles) load_kv(t + 1, (t + 1) & 1);
        CP_COMMIT();

        const int n0 = t * FBN;
        if (n0 > m0 + w * 16 + 15) continue;

        const uint32_t st  = smem + (t & 1) * FSTG;
        const uint32_t Khs = st;
        const uint32_t Kls = st + KT_BYTES;
        const uint32_t Vhs = st + 2 * KT_BYTES;

        float s8[8][4];
#pragma unroll
        for (int nt = 0; nt < 8; nt++)
#pragma unroll
            for (int q = 0; q < 4; q++) s8[nt][q] = 0.f;

#pragma unroll
        for (int j = 0; j < 8; j++) {
#pragma unroll
            for (int nt = 0; nt < 8; nt += 2) {
                uint32_t kb4[4], kl4[4];
                const uint32_t a = (uint32_t)(((nt + npair) * 8 + rlane) * KP
                                              + j * 16 + khalf * 8) * 2;
                ldsm4(Khs + a, kb4);
                ldsm4(Kls + a, kl4);
                mma_bf16(s8[nt],     qh[j], kb4);
                mma_bf16(s8[nt],     qh[j], kl4);
                mma_bf16(s8[nt],     ql[j], kb4);
                mma_bf16(s8[nt + 1], qh[j], kb4 + 2);
                mma_bf16(s8[nt + 1], qh[j], kl4 + 2);
                mma_bf16(s8[nt + 1], ql[j], kb4 + 2);
            }
        }

        if (t >= ntiles - 2) {
            const int colc = n0 + (lane & 3) * 2;
#pragma unroll
            for (int nt = 0; nt < 8; nt++) {
                const int cg = colc + nt * 8;
                if (cg     > rowg0) s8[nt][0] = -1e30f;
                if (cg + 1 > rowg0) s8[nt][1] = -1e30f;
                if (cg     > rowg1) s8[nt][2] = -1e30f;
                if (cg + 1 > rowg1) s8[nt][3] = -1e30f;
            }
        }

        float mx0 = -1e30f, mx1 = -1e30f;
#pragma unroll
        for (int nt = 0; nt < 8; nt++) {
            mx0 = fmaxf(mx0, fmaxf(s8[nt][0], s8[nt][1]));
            mx1 = fmaxf(mx1, fmaxf(s8[nt][2], s8[nt][3]));
        }
        mx0 = fmaxf(mx0, __shfl_xor_sync(0xffffffffu, mx0, 1));
        mx0 = fmaxf(mx0, __shfl_xor_sync(0xffffffffu, mx0, 2));
        mx1 = fmaxf(mx1, __shfl_xor_sync(0xffffffffu, mx1, 1));
        mx1 = fmaxf(mx1, __shfl_xor_sync(0xffffffffu, mx1, 2));

        const float mn0 = fmaxf(mrow0, mx0);
        const float mn1 = fmaxf(mrow1, mx1);
        const float alpha0 = __expf(mrow0 - mn0);
        const float alpha1 = __expf(mrow1 - mn1);

        float sum0 = 0.f, sum1 = 0.f;
#pragma unroll
        for (int nt = 0; nt < 8; nt++) {
            s8[nt][0] = __expf(s8[nt][0] - mn0);
            s8[nt][1] = __expf(s8[nt][1] - mn0);
            s8[nt][2] = __expf(s8[nt][2] - mn1);
            s8[nt][3] = __expf(s8[nt][3] - mn1);
            sum0 += s8[nt][0] + s8[nt][1];
            sum1 += s8[nt][2] + s8[nt][3];
        }
        sum0 += __shfl_xor_sync(0xffffffffu, sum0, 1);
        sum0 += __shfl_xor_sync(0xffffffffu, sum0, 2);
        sum1 += __shfl_xor_sync(0xffffffffu, sum1, 1);
        sum1 += __shfl_xor_sync(0xffffffffu, sum1, 2);

        lrow0 = lrow0 * alpha0 + sum0;
        lrow1 = lrow1 * alpha1 + sum1;
        mrow0 = mn0; mrow1 = mn1;

#pragma unroll
        for (int nt = 0; nt < 16; nt++) {
            o[nt][0] *= alpha0; o[nt][1] *= alpha0;
            o[nt][2] *= alpha1; o[nt][3] *= alpha1;
        }

#pragma unroll
        for (int kt = 0; kt < 4; kt++) {
            uint32_t ph4[4];
            {
                const float* p0 = s8[2 * kt];
                const float* p1 = s8[2 * kt + 1];
                ph4[0] = pack_f16x2(p0[0], p0[1]);
                ph4[1] = pack_f16x2(p0[2], p0[3]);
                ph4[2] = pack_f16x2(p1[0], p1[1]);
                ph4[3] = pack_f16x2(p1[2], p1[3]);
            }
#pragma unroll
            for (int nt = 0; nt < 16; nt += 2) {
                uint32_t vh4[4];
                const uint32_t a = (uint32_t)((kt * 16 + khalf * 8 + rlane) * KP
                                              + (nt + npair) * 8) * 2;
                ldsm4t(Vhs + a, vh4);
                mma_f16(o[nt],     ph4, vh4);
                mma_f16(o[nt + 1], ph4, vh4 + 2);
            }
        }
    }

    const float inv0 = 1.f / lrow0;
    const float inv1 = 1.f / lrow1;
    const size_t base0 = ((size_t)(b * L + rowg0) * H + h) * HD;
    const size_t base1 = base0 + (size_t)8 * H * HD;
#pragma unroll
    for (int nt = 0; nt < 16; nt++) {
        const int col = nt * 8 + (lane & 3) * 2;
        const float f0 = o[nt][0] * inv0, f1 = o[nt][1] * inv0;
        const float f2 = o[nt][2] * inv1, f3 = o[nt][3] * inv1;
        const float h0 = bf16_round(f0), h1 = bf16_round(f1);
        const float h2 = bf16_round(f2), h3 = bf16_round(f3);
        *(uint32_t*)&Ah[base0 + col] = pack_bf16x2(f0, f1);
        *(uint32_t*)&Ah[base1 + col] = pack_bf16x2(f2, f3);
        *(uint32_t*)&Al[base0 + col] = pack_bf16x2(f0 - h0, f1 - h1);
        *(uint32_t*)&Al[base1 + col] = pack_bf16x2(f2 - h2, f3 - h3);
    }
}

// ===========================================================================
extern "C" void kernel_launch(void* const* d_in, const int* in_sizes, int n_in,
                              void* d_out, int out_size)
{
    (void)in_sizes; (void)n_in; (void)out_size;
    const float* x    = (const float*)d_in[0];
    const float* cosb = (const float*)d_in[1];
    const float* sinb = (const float*)d_in[2];
    const float* Wq   = (const float*)d_in[3];
    const float* bq   = (const float*)d_in[4];
    const float* Wkv  = (const float*)d_in[5];
    const float* bkv  = (const float*)d_in[6];
    const float* Wo   = (const float*)d_in[7];
    const float* bo   = (const float*)d_in[8];
    float* out = (float*)d_out;

    float *bqkv;
    __nv_bfloat16 *xh, *xl, *wch, *wcl, *woh, *wol;
    __nv_bfloat16 *qh, *ql, *kh, *kl, *ah, *al;
    __half *vh;
    cudaGetSymbolAddress((void**)&bqkv, g_bqkv);
    cudaGetSymbolAddress((void**)&xh,  g_xh);
    cudaGetSymbolAddress((void**)&xl,  g_xl);
    cudaGetSymbolAddress((void**)&wch, g_wch);
    cudaGetSymbolAddress((void**)&wcl, g_wcl);
    cudaGetSymbolAddress((void**)&woh, g_woh);
    cudaGetSymbolAddress((void**)&wol, g_wol);
    cudaGetSymbolAddress((void**)&qh,  g_qh);
    cudaGetSymbolAddress((void**)&ql,  g_ql);
    cudaGetSymbolAddress((void**)&kh,  g_kh);
    cudaGetSymbolAddress((void**)&kl,  g_kl);
    cudaGetSymbolAddress((void**)&vh,  g_vh);
    cudaGetSymbolAddress((void**)&ah,  g_ah);
    cudaGetSymbolAddress((void**)&al,  g_al);

    const int gemm_smem = 1024 + 2 * STAGE_B2;   // ~197 KB
    cudaFuncSetAttribute(gemm_bf16x3<0>, cudaFuncAttributeMaxDynamicSharedMemorySize,
                         gemm_smem);
    cudaFuncSetAttribute(gemm_bf16x3<1>, cudaFuncAttributeMaxDynamicSharedMemorySize,
                         gemm_smem);
    const int fa_smem = 2 * FSTG;
    cudaFuncSetAttribute(flash_mma, cudaFuncAttributeMaxDynamicSharedMemorySize,
                         fa_smem);

    // fused conversion: x + concat(Wq,Wkv) + Wo + concat bias
    cvt_all<<<(N4_TOT + 255) / 256, 256>>>(x, Wq, Wkv, Wo, bq, bkv,
                                           xh, xl, wch, wcl, woh, wol, bqkv);

    // fused QKV projection with RoPE+split epilogue
    gemm_bf16x3<0><<<dim3(QKVD / 128, M_TOK / 256), 512, gemm_smem>>>(
        xh, xl, wch, wcl, bqkv, nullptr, cosb, sinb, qh, ql, kh, kl, vh);

    // tensor-core flash attention -> Ah/Al splits
    flash_mma<<<dim3(L / FBM, B * H), 256, fa_smem>>>(
        qh, ql, kh, kl, vh, ah, al);

    // O projection
    gemm_bf16x3<1><<<dim3(D / 128, M_TOK / 256), 512, gemm_smem>>>(
        ah, al, woh, wol, bo, out, nullptr, nullptr,
        nullptr, nullptr, nullptr, nullptr, nullptr);
}